// round 3
// baseline (speedup 1.0000x reference)
#include <cuda_runtime.h>
#include <cstdint>

// ---------------- problem constants ----------------
#define N_NODES 50000
#define F_IN    512
#define F_H     256
#define F_OUT   128
#define E_EDGES 800000

// ---------------- scratch (static device globals; no runtime alloc) --------
__device__ int   g_is64;                               // 1 if edge_index is int64
__device__ int   g_deg [N_NODES];
__device__ float g_dinv[N_NODES];
__device__ float g_h1  [(size_t)N_NODES * F_H];        // X @ W1
__device__ float g_agg1[(size_t)N_NODES * F_H];        // aggregated layer1 (then relu+dropout in place)
__device__ float g_h2  [(size_t)N_NODES * F_OUT];      // dropped @ W2
__device__ float g_agg2[(size_t)N_NODES * F_OUT];      // aggregated layer2

// ---------------- edge index access (int32 or int64) ----------------
__device__ __forceinline__ int edge_at(const void* ei, long long i) {
    if (g_is64) return (int)((const long long*)ei)[i];
    return ((const int*)ei)[i];
}

// Detect dtype: int64 little-endian -> all odd 32-bit words are 0 (values < 50000).
__global__ void k_detect(const int* ei32) {
    __shared__ int any_nonzero;
    if (threadIdx.x == 0) any_nonzero = 0;
    __syncthreads();
    if (ei32[2 * threadIdx.x + 1] != 0) atomicOr(&any_nonzero, 1);
    __syncthreads();
    if (threadIdx.x == 0) g_is64 = (any_nonzero == 0) ? 1 : 0;
}

// ---------------- degree / norm ----------------
__global__ void k_zero_deg() {
    int i = blockIdx.x * blockDim.x + threadIdx.x;
    if (i < N_NODES) g_deg[i] = 0;
}
__global__ void k_degree(const void* ei) {
    int e = blockIdx.x * blockDim.x + threadIdx.x;
    if (e < E_EDGES) atomicAdd(&g_deg[edge_at(ei, (long long)E_EDGES + e)], 1);
}
__global__ void k_dinv() {
    int i = blockIdx.x * blockDim.x + threadIdx.x;
    if (i < N_NODES) g_dinv[i] = rsqrtf((float)(g_deg[i] + 1));   // +1 self loop
}

// ---------------- FP32 SGEMM: C[M,Nd] = A[M,Kd] * B[Kd,Nd] ----------------
// BM=128, BN=64, BK=16, 256 threads, 8x4 microtile.
template <int Kd, int Nd>
__global__ void __launch_bounds__(256) k_gemm(const float* __restrict__ A,
                                              const float* __restrict__ B,
                                              float* __restrict__ C, int M) {
    __shared__ float As[16][128];
    __shared__ float Bs[16][64];
    const int t  = threadIdx.x;
    const int tx = t & 15;        // 0..15 -> 4 cols each
    const int ty = t >> 4;        // 0..15 -> 8 rows each
    const int brow = blockIdx.y * 128;
    const int bcol = blockIdx.x * 64;

    float acc[8][4];
#pragma unroll
    for (int m = 0; m < 8; m++)
#pragma unroll
        for (int n = 0; n < 4; n++) acc[m][n] = 0.0f;

    for (int kt = 0; kt < Kd; kt += 16) {
        // A tile: 128 rows x 16 k, transposed into As[k][row]. 512 float4s / 256 thr.
#pragma unroll
        for (int l = 0; l < 2; l++) {
            int f4  = t + l * 256;          // 0..511
            int row = f4 >> 2;              // 0..127
            int kc  = (f4 & 3) * 4;         // 0,4,8,12
            int gr  = brow + row;
            float4 av = make_float4(0.f, 0.f, 0.f, 0.f);
            if (gr < M) av = *(const float4*)(A + (size_t)gr * Kd + kt + kc);
            As[kc + 0][row] = av.x;
            As[kc + 1][row] = av.y;
            As[kc + 2][row] = av.z;
            As[kc + 3][row] = av.w;
        }
        // B tile: 16 k x 64 cols. 256 float4s / 256 thr.
        {
            int k  = t >> 4;                // 0..15
            int c4 = (t & 15) * 4;          // 0..60
            float4 bv = *(const float4*)(B + (size_t)(kt + k) * Nd + bcol + c4);
            *(float4*)&Bs[k][c4] = bv;
        }
        __syncthreads();
#pragma unroll
        for (int kk = 0; kk < 16; kk++) {
            float4 a0 = *(const float4*)&As[kk][ty * 8];
            float4 a1 = *(const float4*)&As[kk][ty * 8 + 4];
            float4 b0 = *(const float4*)&Bs[kk][tx * 4];
            float a[8] = {a0.x, a0.y, a0.z, a0.w, a1.x, a1.y, a1.z, a1.w};
            float b[4] = {b0.x, b0.y, b0.z, b0.w};
#pragma unroll
            for (int m = 0; m < 8; m++)
#pragma unroll
                for (int n = 0; n < 4; n++)
                    acc[m][n] = fmaf(a[m], b[n], acc[m][n]);
        }
        __syncthreads();
    }
#pragma unroll
    for (int m = 0; m < 8; m++) {
        int gr = brow + ty * 8 + m;
        if (gr < M)
            *(float4*)(C + (size_t)gr * Nd + bcol + tx * 4) =
                make_float4(acc[m][0], acc[m][1], acc[m][2], acc[m][3]);
    }
}

// ---------------- self-loop init: out = dinv[i]^2 * h ----------------
template <int F>
__global__ void k_selfinit(const float* __restrict__ h, float* __restrict__ out) {
    long long i = (long long)blockIdx.x * blockDim.x + threadIdx.x;  // float4 idx
    const long long total = (long long)N_NODES * (F / 4);
    if (i >= total) return;
    int node = (int)(i / (F / 4));
    float d = g_dinv[node];
    float s = d * d;
    float4 v = ((const float4*)h)[i];
    v.x *= s; v.y *= s; v.z *= s; v.w *= s;
    ((float4*)out)[i] = v;
}

// ---------------- edge scatter: out[dst] += dinv[src]*dinv[dst] * h[src] ---
template <int F>
__global__ void __launch_bounds__(256) k_scatter(const void* __restrict__ ei,
                                                 const float* __restrict__ h,
                                                 float* __restrict__ out) {
    constexpr int F4  = F / 4;       // lanes per edge
    constexpr int EPB = 256 / F4;    // edges per block
    int lane = threadIdx.x & (F4 - 1);
    int e    = blockIdx.x * EPB + threadIdx.x / F4;
    if (e >= E_EDGES) return;
    int src = edge_at(ei, e);
    int dst = edge_at(ei, (long long)E_EDGES + e);
    float nrm = g_dinv[src] * g_dinv[dst];
    float4 v = ((const float4*)(h + (size_t)src * F))[lane];
    v.x *= nrm; v.y *= nrm; v.z *= nrm; v.w *= nrm;
    float* p = out + (size_t)dst * F + lane * 4;
    asm volatile("red.global.add.v4.f32 [%0], {%1, %2, %3, %4};"
                 :: "l"(p), "f"(v.x), "f"(v.y), "f"(v.z), "f"(v.w)
                 : "memory");
}

// ---------------- threefry2x32 (JAX default PRNG), key = (0, 42) ----------
__device__ __forceinline__ void threefry_0_42(unsigned c0, unsigned c1,
                                              unsigned& o0, unsigned& o1) {
    const unsigned ks0 = 0u, ks1 = 42u, ks2 = 0u ^ 42u ^ 0x1BD11BDAu;
    unsigned x0 = c0 + ks0, x1 = c1 + ks1;
#define TF_RND(r) { x0 += x1; x1 = __funnelshift_l(x1, x1, (r)); x1 ^= x0; }
    TF_RND(13) TF_RND(15) TF_RND(26) TF_RND(6)
    x0 += ks1; x1 += ks2 + 1u;
    TF_RND(17) TF_RND(29) TF_RND(16) TF_RND(24)
    x0 += ks2; x1 += ks0 + 2u;
    TF_RND(13) TF_RND(15) TF_RND(26) TF_RND(6)
    x0 += ks0; x1 += ks1 + 3u;
    TF_RND(17) TF_RND(29) TF_RND(16) TF_RND(24)
    x0 += ks1; x1 += ks2 + 4u;
    TF_RND(13) TF_RND(15) TF_RND(26) TF_RND(6)
    x0 += ks2; x1 += ks0 + 5u;
#undef TF_RND
    o0 = x0; o1 = x1;
}

// ---------------- bias + relu + dropout (in place on g_agg1) --------------
// JAX >= 0.4.30 default: jax_threefry_partitionable=True. Element i of the
// flattened array uses the 64-bit index as counter: (hi32(i), lo32(i)) = (0, i)
// for i < 2^32; the 32-bit output is the XOR of the two threefry output lanes.
__global__ void k_relu_dropout(const float* __restrict__ b1) {
    long long i = (long long)blockIdx.x * blockDim.x + threadIdx.x;
    const long long total = (long long)N_NODES * F_H;     // 12,800,000
    if (i >= total) return;
    float v = g_agg1[i] + b1[(int)(i & (F_H - 1))];
    v = fmaxf(v, 0.0f);

    unsigned r0, r1;
    threefry_0_42(0u, (unsigned)i, r0, r1);      // counter = (hi, lo) = (0, i)
    unsigned bits = r0 ^ r1;                     // partitionable 32-bit fold
    float u = __uint_as_float((bits >> 9) | 0x3f800000u) - 1.0f;  // [0,1)
    g_agg1[i] = (u < 0.8f) ? v * 1.25f : 0.0f;   // keep-prob 0.8, scale 1/0.8
}

// ---------------- row softmax (128 cols): one warp per row ----------------
__global__ void k_softmax(const float* __restrict__ b2, float* __restrict__ out) {
    int gwarp = (blockIdx.x * blockDim.x + threadIdx.x) >> 5;
    int lane  = threadIdx.x & 31;
    if (gwarp >= N_NODES) return;
    float4 v  = ((const float4*)(g_agg2 + (size_t)gwarp * F_OUT))[lane];
    float4 bb = ((const float4*)b2)[lane];
    v.x += bb.x; v.y += bb.y; v.z += bb.z; v.w += bb.w;
    float m = fmaxf(fmaxf(v.x, v.y), fmaxf(v.z, v.w));
#pragma unroll
    for (int off = 16; off > 0; off >>= 1)
        m = fmaxf(m, __shfl_xor_sync(0xffffffffu, m, off));
    v.x = expf(v.x - m); v.y = expf(v.y - m);
    v.z = expf(v.z - m); v.w = expf(v.w - m);
    float s = v.x + v.y + v.z + v.w;
#pragma unroll
    for (int off = 16; off > 0; off >>= 1)
        s += __shfl_xor_sync(0xffffffffu, s, off);
    float inv = 1.0f / s;
    v.x *= inv; v.y *= inv; v.z *= inv; v.w *= inv;
    ((float4*)out)[(size_t)gwarp * (F_OUT / 4) + lane] = v;
}

// ---------------- launcher ----------------
extern "C" void kernel_launch(void* const* d_in, const int* in_sizes, int n_in,
                              void* d_out, int out_size) {
    const float* x  = (const float*)d_in[0];
    const void*  ei = d_in[1];
    const float* W1 = (const float*)d_in[2];
    const float* b1 = (const float*)d_in[3];
    const float* W2 = (const float*)d_in[4];
    const float* b2 = (const float*)d_in[5];
    float* out = (float*)d_out;

    float* h1   = nullptr; cudaGetSymbolAddress((void**)&h1,   g_h1);
    float* agg1 = nullptr; cudaGetSymbolAddress((void**)&agg1, g_agg1);
    float* h2   = nullptr; cudaGetSymbolAddress((void**)&h2,   g_h2);
    float* agg2 = nullptr; cudaGetSymbolAddress((void**)&agg2, g_agg2);

    // 0. edge dtype detection + degree/norm
    k_detect<<<1, 1024>>>((const int*)ei);
    k_zero_deg<<<(N_NODES + 255) / 256, 256>>>();
    k_degree<<<(E_EDGES + 255) / 256, 256>>>(ei);
    k_dinv<<<(N_NODES + 255) / 256, 256>>>();

    // 1. h1 = x @ W1
    k_gemm<F_IN, F_H><<<dim3(F_H / 64, (N_NODES + 127) / 128), 256>>>(x, W1, h1, N_NODES);

    // 2. agg1 = Â h1 (self-loop init + edge scatter)
    k_selfinit<F_H><<<(N_NODES * (F_H / 4) + 255) / 256, 256>>>(h1, agg1);
    k_scatter<F_H><<<(E_EDGES + 3) / 4, 256>>>(ei, h1, agg1);

    // 3. +b1, relu, dropout (JAX partitionable threefry mask), in place
    k_relu_dropout<<<(int)(((long long)N_NODES * F_H + 255) / 256), 256>>>(b1);

    // 4. h2 = dropped @ W2
    k_gemm<F_H, F_OUT><<<dim3(F_OUT / 64, (N_NODES + 127) / 128), 256>>>(agg1, W2, h2, N_NODES);

    // 5. agg2 = Â h2
    k_selfinit<F_OUT><<<(N_NODES * (F_OUT / 4) + 255) / 256, 256>>>(h2, agg2);
    k_scatter<F_OUT><<<(E_EDGES + 7) / 8, 256>>>(ei, h2, agg2);

    // 6. softmax rows -> d_out
    k_softmax<<<(N_NODES * 32 + 255) / 256, 256>>>(b2, out);
}

// round 6
// speedup vs baseline: 1.4665x; 1.4665x over previous
#include <cuda_runtime.h>
#include <cstdint>

// ---------------- problem constants ----------------
#define N_NODES 50000
#define F_IN    512
#define F_H     256
#define F_OUT   128
#define E_EDGES 800000

// ---------------- scratch (static device globals; no runtime alloc) --------
__device__ int   g_is64;
__device__ int   g_deg [N_NODES];
__device__ float g_dinv[N_NODES];
__device__ float g_h1  [(size_t)N_NODES * F_H];
__device__ float g_agg1[(size_t)N_NODES * F_H];
__device__ float g_h2  [(size_t)N_NODES * F_OUT];
__device__ float g_agg2[(size_t)N_NODES * F_OUT];
// W transposed to [N][K], tf32(rna) bit patterns
__device__ uint32_t g_w1t[F_IN * F_H];
__device__ uint32_t g_w2t[F_H * F_OUT];

// ---------------- helpers ----------------
__device__ __forceinline__ uint32_t f2tf32(float f) {
    uint32_t r; asm("cvt.rna.tf32.f32 %0, %1;" : "=r"(r) : "f"(f)); return r;
}

// ---------------- edge index access (int32 or int64) ----------------
__device__ __forceinline__ int edge_at(const void* ei, long long i) {
    if (g_is64) return (int)((const long long*)ei)[i];
    return ((const int*)ei)[i];
}
__global__ void k_detect(const int* ei32) {
    __shared__ int any_nonzero;
    if (threadIdx.x == 0) any_nonzero = 0;
    __syncthreads();
    if (ei32[2 * threadIdx.x + 1] != 0) atomicOr(&any_nonzero, 1);
    __syncthreads();
    if (threadIdx.x == 0) g_is64 = (any_nonzero == 0) ? 1 : 0;
}

// ---------------- degree / norm ----------------
__global__ void k_zero_deg() {
    int i = blockIdx.x * blockDim.x + threadIdx.x;
    if (i < N_NODES) g_deg[i] = 0;
}
__global__ void k_degree(const void* ei) {
    int e = blockIdx.x * blockDim.x + threadIdx.x;
    if (e < E_EDGES) atomicAdd(&g_deg[edge_at(ei, (long long)E_EDGES + e)], 1);
}
__global__ void k_dinv() {
    int i = blockIdx.x * blockDim.x + threadIdx.x;
    if (i < N_NODES) g_dinv[i] = rsqrtf((float)(g_deg[i] + 1));
}

// ---------------- W prep: transpose to [N][K], tf32(rna) ----------
template <int Kd, int Nd>
__global__ void k_wprep(const float* __restrict__ W, uint32_t* __restrict__ Wt) {
    int i = blockIdx.x * blockDim.x + threadIdx.x;
    if (i >= Kd * Nd) return;
    int k = i / Nd, n = i % Nd;
    Wt[(size_t)n * Kd + k] = f2tf32(W[i]);
}

// ---------------- tensor-core GEMM via mma.sync (tf32) --------------------
// C[M,Nd] = A[M,Kd] * Bt[Nd,Kd]^T.  CTA: 128 rows x Nd cols, 512 threads.
// Warp grid 2(M) x 8(N): warp tile 64 x (Nd/8). BK=32, smem stride 36 (pad).
template <int Kd, int Nd>
__global__ void __launch_bounds__(512) k_gemm_mma(const float* __restrict__ A,
                                                  const uint32_t* __restrict__ Bt,
                                                  float* __restrict__ C, int M) {
    constexpr int WN = Nd / 8;    // per-warp N width (32 or 16)
    constexpr int NT = WN / 8;    // n-tiles per warp (4 or 2)
    constexpr int STR = 36;       // smem row stride in words (32 + 4 pad)
    extern __shared__ char smem[];
    uint32_t* As = (uint32_t*)smem;                       // [128][STR]
    uint32_t* Bs = (uint32_t*)(smem + 128 * STR * 4);     // [Nd][STR]

    const int t    = threadIdx.x;
    const int lane = t & 31, wid = t >> 5;
    const int gid  = lane >> 2, tig = lane & 3;
    const int wm   = (wid & 1) * 64;
    const int wn   = (wid >> 1) * WN;
    const int brow = blockIdx.x * 128;

    float c[4][NT][4];
#pragma unroll
    for (int mt = 0; mt < 4; mt++)
#pragma unroll
        for (int nt = 0; nt < NT; nt++)
#pragma unroll
            for (int i = 0; i < 4; i++) c[mt][nt][i] = 0.0f;

    for (int kt = 0; kt < Kd / 32; kt++) {
        // ---- A tile: 128 x 32 fp32 -> tf32(rna), 1024 uint4 / 512 thr ----
#pragma unroll
        for (int it = 0; it < 2; it++) {
            int f4  = it * 512 + t;
            int row = f4 >> 3, cq = f4 & 7;
            float4 v = make_float4(0.f, 0.f, 0.f, 0.f);
            if (brow + row < M)
                v = *(const float4*)(A + (size_t)(brow + row) * Kd + kt * 32 + cq * 4);
            uint4 u;
            u.x = f2tf32(v.x); u.y = f2tf32(v.y);
            u.z = f2tf32(v.z); u.w = f2tf32(v.w);
            *(uint4*)(As + row * STR + cq * 4) = u;
        }
        // ---- B tile: Nd x 32 (pre-converted), Nd*8 uint4 / 512 thr ----
#pragma unroll
        for (int it = 0; it < Nd / 64; it++) {
            int f4 = it * 512 + t;
            int n  = f4 >> 3, cq = f4 & 7;
            uint4 u = *(const uint4*)(Bt + (size_t)n * Kd + kt * 32 + cq * 4);
            *(uint4*)(Bs + n * STR + cq * 4) = u;
        }
        __syncthreads();

#pragma unroll
        for (int ks = 0; ks < 4; ks++) {
            uint32_t a[4][4], b[NT][2];
#pragma unroll
            for (int mt = 0; mt < 4; mt++) {
                int r = wm + mt * 16;
                a[mt][0] = As[(r + gid)     * STR + ks * 8 + tig];
                a[mt][1] = As[(r + gid + 8) * STR + ks * 8 + tig];
                a[mt][2] = As[(r + gid)     * STR + ks * 8 + tig + 4];
                a[mt][3] = As[(r + gid + 8) * STR + ks * 8 + tig + 4];
            }
#pragma unroll
            for (int nt = 0; nt < NT; nt++) {
                int n = wn + nt * 8 + gid;
                b[nt][0] = Bs[n * STR + ks * 8 + tig];
                b[nt][1] = Bs[n * STR + ks * 8 + tig + 4];
            }
#pragma unroll
            for (int mt = 0; mt < 4; mt++)
#pragma unroll
                for (int nt = 0; nt < NT; nt++)
                    asm volatile(
                        "mma.sync.aligned.m16n8k8.row.col.f32.tf32.tf32.f32 "
                        "{%0,%1,%2,%3}, {%4,%5,%6,%7}, {%8,%9}, {%0,%1,%2,%3};"
                        : "+f"(c[mt][nt][0]), "+f"(c[mt][nt][1]),
                          "+f"(c[mt][nt][2]), "+f"(c[mt][nt][3])
                        : "r"(a[mt][0]), "r"(a[mt][1]), "r"(a[mt][2]), "r"(a[mt][3]),
                          "r"(b[nt][0]), "r"(b[nt][1]));
        }
        __syncthreads();
    }

    // ---- epilogue: direct STG.64 ----
#pragma unroll
    for (int mt = 0; mt < 4; mt++)
#pragma unroll
        for (int nt = 0; nt < NT; nt++) {
            int col = wn + nt * 8 + tig * 2;
            int r0  = brow + wm + mt * 16 + gid;
            int r1  = r0 + 8;
            if (r0 < M)
                *(float2*)(C + (size_t)r0 * Nd + col) =
                    make_float2(c[mt][nt][0], c[mt][nt][1]);
            if (r1 < M)
                *(float2*)(C + (size_t)r1 * Nd + col) =
                    make_float2(c[mt][nt][2], c[mt][nt][3]);
        }
}

// ---------------- self-loop init: out = dinv[i]^2 * h ----------------
template <int F>
__global__ void k_selfinit(const float* __restrict__ h, float* __restrict__ out) {
    long long i = (long long)blockIdx.x * blockDim.x + threadIdx.x;
    const long long total = (long long)N_NODES * (F / 4);
    if (i >= total) return;
    int node = (int)(i / (F / 4));
    float d = g_dinv[node];
    float s = d * d;
    float4 v = ((const float4*)h)[i];
    v.x *= s; v.y *= s; v.z *= s; v.w *= s;
    ((float4*)out)[i] = v;
}

// ---------------- edge scatter: out[dst] += dinv[src]*dinv[dst]*h[src] -----
template <int F>
__global__ void __launch_bounds__(256) k_scatter(const void* __restrict__ ei,
                                                 const float* __restrict__ h,
                                                 float* __restrict__ out) {
    constexpr int F4 = F / 4;
    constexpr int EPB = 256 / F4;
    int lane = threadIdx.x & (F4 - 1);
    int e = blockIdx.x * EPB + threadIdx.x / F4;
    if (e >= E_EDGES) return;
    int src = edge_at(ei, e);
    int dst = edge_at(ei, (long long)E_EDGES + e);
    float nrm = g_dinv[src] * g_dinv[dst];
    float4 v = ((const float4*)(h + (size_t)src * F))[lane];
    v.x *= nrm; v.y *= nrm; v.z *= nrm; v.w *= nrm;
    float* p = out + (size_t)dst * F + lane * 4;
    asm volatile("red.global.add.v4.f32 [%0], {%1, %2, %3, %4};"
                 :: "l"(p), "f"(v.x), "f"(v.y), "f"(v.z), "f"(v.w) : "memory");
}

// ---------------- threefry2x32 key (0,42) ----------------
__device__ __forceinline__ void threefry_0_42(unsigned c0, unsigned c1,
                                              unsigned& o0, unsigned& o1) {
    const unsigned ks0 = 0u, ks1 = 42u, ks2 = 0u ^ 42u ^ 0x1BD11BDAu;
    unsigned x0 = c0 + ks0, x1 = c1 + ks1;
#define TF_RND(r) { x0 += x1; x1 = __funnelshift_l(x1, x1, (r)); x1 ^= x0; }
    TF_RND(13) TF_RND(15) TF_RND(26) TF_RND(6)
    x0 += ks1; x1 += ks2 + 1u;
    TF_RND(17) TF_RND(29) TF_RND(16) TF_RND(24)
    x0 += ks2; x1 += ks0 + 2u;
    TF_RND(13) TF_RND(15) TF_RND(26) TF_RND(6)
    x0 += ks0; x1 += ks1 + 3u;
    TF_RND(17) TF_RND(29) TF_RND(16) TF_RND(24)
    x0 += ks1; x1 += ks2 + 4u;
    TF_RND(13) TF_RND(15) TF_RND(26) TF_RND(6)
    x0 += ks2; x1 += ks0 + 5u;
#undef TF_RND
    o0 = x0; o1 = x1;
}

// ---------------- bias + relu + dropout (JAX partitionable threefry) -------
__global__ void k_relu_dropout(const float* __restrict__ b1) {
    long long i = (long long)blockIdx.x * blockDim.x + threadIdx.x;
    const long long total = (long long)N_NODES * F_H;
    if (i >= total) return;
    float v = g_agg1[i] + b1[(int)(i & (F_H - 1))];
    v = fmaxf(v, 0.0f);
    unsigned r0, r1;
    threefry_0_42(0u, (unsigned)i, r0, r1);
    unsigned bits = r0 ^ r1;
    float u = __uint_as_float((bits >> 9) | 0x3f800000u) - 1.0f;
    g_agg1[i] = (u < 0.8f) ? v * 1.25f : 0.0f;
}

// ---------------- row softmax (128 cols): one warp per row ----------------
__global__ void k_softmax(const float* __restrict__ b2, float* __restrict__ out) {
    int gwarp = (blockIdx.x * blockDim.x + threadIdx.x) >> 5;
    int lane = threadIdx.x & 31;
    if (gwarp >= N_NODES) return;
    float4 v  = ((const float4*)(g_agg2 + (size_t)gwarp * F_OUT))[lane];
    float4 bb = ((const float4*)b2)[lane];
    v.x += bb.x; v.y += bb.y; v.z += bb.z; v.w += bb.w;
    float m = fmaxf(fmaxf(v.x, v.y), fmaxf(v.z, v.w));
#pragma unroll
    for (int off = 16; off > 0; off >>= 1)
        m = fmaxf(m, __shfl_xor_sync(0xffffffffu, m, off));
    v.x = expf(v.x - m); v.y = expf(v.y - m);
    v.z = expf(v.z - m); v.w = expf(v.w - m);
    float s = v.x + v.y + v.z + v.w;
#pragma unroll
    for (int off = 16; off > 0; off >>= 1)
        s += __shfl_xor_sync(0xffffffffu, s, off);
    float inv = 1.0f / s;
    v.x *= inv; v.y *= inv; v.z *= inv; v.w *= inv;
    ((float4*)out)[(size_t)gwarp * (F_OUT / 4) + lane] = v;
}

// ---------------- launcher ----------------
extern "C" void kernel_launch(void* const* d_in, const int* in_sizes, int n_in,
                              void* d_out, int out_size) {
    const float* x  = (const float*)d_in[0];
    const void*  ei = d_in[1];
    const float* W1 = (const float*)d_in[2];
    const float* b1 = (const float*)d_in[3];
    const float* W2 = (const float*)d_in[4];
    const float* b2 = (const float*)d_in[5];
    float* out = (float*)d_out;

    float* h1;   cudaGetSymbolAddress((void**)&h1,   g_h1);
    float* agg1; cudaGetSymbolAddress((void**)&agg1, g_agg1);
    float* h2;   cudaGetSymbolAddress((void**)&h2,   g_h2);
    float* agg2; cudaGetSymbolAddress((void**)&agg2, g_agg2);
    uint32_t* w1t; cudaGetSymbolAddress((void**)&w1t, g_w1t);
    uint32_t* w2t; cudaGetSymbolAddress((void**)&w2t, g_w2t);

    constexpr int SMEM1 = (128 * 36 + F_H  * 36) * 4;  // 55296
    constexpr int SMEM2 = (128 * 36 + F_OUT * 36) * 4; // 36864
    cudaFuncSetAttribute(k_gemm_mma<F_IN, F_H>,
                         cudaFuncAttributeMaxDynamicSharedMemorySize, SMEM1);
    cudaFuncSetAttribute(k_gemm_mma<F_H, F_OUT>,
                         cudaFuncAttributeMaxDynamicSharedMemorySize, SMEM2);

    const int MTILES = (N_NODES + 127) / 128;  // 391

    // 0. edge dtype detection + degree/norm + W prep
    k_detect<<<1, 1024>>>((const int*)ei);
    k_zero_deg<<<(N_NODES + 255) / 256, 256>>>();
    k_degree<<<(E_EDGES + 255) / 256, 256>>>(ei);
    k_dinv<<<(N_NODES + 255) / 256, 256>>>();
    k_wprep<F_IN, F_H ><<<(F_IN * F_H  + 255) / 256, 256>>>(W1, w1t);
    k_wprep<F_H,  F_OUT><<<(F_H * F_OUT + 255) / 256, 256>>>(W2, w2t);

    // 1. h1 = x @ W1  (tf32 mma.sync)
    k_gemm_mma<F_IN, F_H><<<MTILES, 512, SMEM1>>>(x, w1t, h1, N_NODES);

    // 2. agg1 = Â h1
    k_selfinit<F_H><<<(N_NODES * (F_H / 4) + 255) / 256, 256>>>(h1, agg1);
    k_scatter<F_H><<<(E_EDGES + 3) / 4, 256>>>(ei, h1, agg1);

    // 3. +b1, relu, dropout
    k_relu_dropout<<<(int)(((long long)N_NODES * F_H + 255) / 256), 256>>>(b1);

    // 4. h2 = dropped @ W2
    k_gemm_mma<F_H, F_OUT><<<MTILES, 512, SMEM2>>>(agg1, w2t, h2, N_NODES);

    // 5. agg2 = Â h2
    k_selfinit<F_OUT><<<(N_NODES * (F_OUT / 4) + 255) / 256, 256>>>(h2, agg2);
    k_scatter<F_OUT><<<(E_EDGES + 7) / 8, 256>>>(ei, h2, agg2);

    // 6. softmax rows -> d_out
    k_softmax<<<(N_NODES * 32 + 255) / 256, 256>>>(b2, out);
}

// round 7
// speedup vs baseline: 2.2934x; 1.5638x over previous
#include <cuda_runtime.h>
#include <cstdint>

// ---------------- problem constants ----------------
#define N_NODES 50000
#define F_IN    512
#define F_H     256
#define F_OUT   128
#define E_EDGES 800000

// ---------------- scratch (static device globals; no runtime alloc) --------
__device__ int   g_is64;
__device__ int   g_deg [N_NODES];
__device__ int   g_cursor[N_NODES];
__device__ int   g_rowstart[N_NODES + 1];
__device__ int   g_csrc[E_EDGES];                    // src ids grouped by dst
__device__ float g_dinv[N_NODES];
__device__ float g_h1  [(size_t)N_NODES * F_H];
__device__ float g_agg1[(size_t)N_NODES * F_H];
__device__ float g_h2  [(size_t)N_NODES * F_OUT];
// W transposed to [N][K], tf32(rna) bit patterns
__device__ uint32_t g_w1t[F_IN * F_H];
__device__ uint32_t g_w2t[F_H * F_OUT];

// ---------------- helpers ----------------
__device__ __forceinline__ uint32_t f2tf32(float f) {
    uint32_t r; asm("cvt.rna.tf32.f32 %0, %1;" : "=r"(r) : "f"(f)); return r;
}
__device__ __forceinline__ uint32_t smem_u32(const void* p) {
    uint32_t a;
    asm("{ .reg .u64 t; cvta.to.shared.u64 t, %1; cvt.u32.u64 %0, t; }" : "=r"(a) : "l"(p));
    return a;
}
__device__ __forceinline__ void cp16(uint32_t s, const void* g) {
    asm volatile("cp.async.cg.shared.global [%0], [%1], 16;" :: "r"(s), "l"(g));
}
__device__ __forceinline__ void cp_commit() {
    asm volatile("cp.async.commit_group;" ::: "memory");
}
template <int N>
__device__ __forceinline__ void cp_wait() {
    asm volatile("cp.async.wait_group %0;" :: "n"(N) : "memory");
}

// ---------------- edge index access (int32 or int64) ----------------
__device__ __forceinline__ int edge_at(const void* ei, long long i) {
    if (g_is64) return (int)((const long long*)ei)[i];
    return ((const int*)ei)[i];
}
__global__ void k_detect(const int* ei32) {
    __shared__ int any_nonzero;
    if (threadIdx.x == 0) any_nonzero = 0;
    __syncthreads();
    if (ei32[2 * threadIdx.x + 1] != 0) atomicOr(&any_nonzero, 1);
    __syncthreads();
    if (threadIdx.x == 0) g_is64 = (any_nonzero == 0) ? 1 : 0;
}

// ---------------- degree / norm / CSR ----------------
__global__ void k_zero2() {
    int i = blockIdx.x * blockDim.x + threadIdx.x;
    if (i < N_NODES) { g_deg[i] = 0; g_cursor[i] = 0; }
}
__global__ void k_degree(const void* ei) {
    int e = blockIdx.x * blockDim.x + threadIdx.x;
    if (e < E_EDGES) atomicAdd(&g_deg[edge_at(ei, (long long)E_EDGES + e)], 1);
}
__global__ void k_dinv() {
    int i = blockIdx.x * blockDim.x + threadIdx.x;
    if (i < N_NODES) g_dinv[i] = rsqrtf((float)(g_deg[i] + 1));
}
// exclusive prefix over g_deg -> g_rowstart. One block of 1024, sequential chunks.
__global__ void k_scan() {
    __shared__ int tmp[1024];
    __shared__ int carry;
    int t = threadIdx.x;
    if (t == 0) carry = 0;
    __syncthreads();
    for (int base = 0; base < N_NODES; base += 1024) {
        int v = (base + t < N_NODES) ? g_deg[base + t] : 0;
        tmp[t] = v;
        __syncthreads();
#pragma unroll
        for (int off = 1; off < 1024; off <<= 1) {
            int x = (t >= off) ? tmp[t - off] : 0;
            __syncthreads();
            tmp[t] += x;
            __syncthreads();
        }
        if (base + t < N_NODES) g_rowstart[base + t] = carry + tmp[t] - v;
        __syncthreads();
        if (t == 0) carry += tmp[1023];
        __syncthreads();
    }
    if (t == 0) g_rowstart[N_NODES] = carry;
}
__global__ void k_fill(const void* ei) {
    int e = blockIdx.x * blockDim.x + threadIdx.x;
    if (e >= E_EDGES) return;
    int src = edge_at(ei, e);
    int dst = edge_at(ei, (long long)E_EDGES + e);
    int pos = g_rowstart[dst] + atomicAdd(&g_cursor[dst], 1);
    g_csrc[pos] = src;
}

// ---------------- W prep: transpose to [N][K], tf32(rna) ----------
template <int Kd, int Nd>
__global__ void k_wprep(const float* __restrict__ W, uint32_t* __restrict__ Wt) {
    int i = blockIdx.x * blockDim.x + threadIdx.x;
    if (i >= Kd * Nd) return;
    int k = i / Nd, n = i % Nd;
    Wt[(size_t)n * Kd + k] = f2tf32(W[i]);
}

// ---------------- tensor-core GEMM via mma.sync (tf32), cp.async x2 -------
// C[M,Nd] = A[M,Kd] * Bt[Nd,Kd]^T.  CTA: 128 rows x Nd, 512 thr, BK=32.
// A fed as raw fp32 bits (HW tf32 truncation); B pre-converted rna.
template <int Kd, int Nd>
__global__ void __launch_bounds__(512) k_gemm_mma(const float* __restrict__ A,
                                                  const uint32_t* __restrict__ Bt,
                                                  float* __restrict__ C, int M) {
    constexpr int WN  = Nd / 8;
    constexpr int NT  = WN / 8;
    constexpr int STR = 36;                  // words; 144 B row stride (16B-mult)
    constexpr int ABYTES = 128 * STR * 4;    // 18432
    constexpr int BBYTES = Nd * STR * 4;
    constexpr int KT = Kd / 32;
    extern __shared__ char smem[];
    const uint32_t sb = smem_u32(smem);

    const int t    = threadIdx.x;
    const int lane = t & 31, wid = t >> 5;
    const int gid  = lane >> 2, tig = lane & 3;
    const int wm   = (wid & 1) * 64;
    const int wn   = (wid >> 1) * WN;
    const int brow = blockIdx.x * 128;

    auto load_tile = [&](int kt, int buf) {
        uint32_t sA = sb + buf * ABYTES;
        uint32_t sB = sb + 2 * ABYTES + buf * BBYTES;
#pragma unroll
        for (int it = 0; it < 2; it++) {
            int f4 = it * 512 + t;
            int row = f4 >> 3, cq = f4 & 7;
            int grow = brow + row; if (grow > M - 1) grow = M - 1;   // clamp: junk rows unused
            cp16(sA + (uint32_t)(row * STR + cq * 4) * 4,
                 A + (size_t)grow * Kd + kt * 32 + cq * 4);
        }
#pragma unroll
        for (int it = 0; it < Nd / 64; it++) {
            int f4 = it * 512 + t;
            int n = f4 >> 3, cq = f4 & 7;
            cp16(sB + (uint32_t)(n * STR + cq * 4) * 4,
                 Bt + (size_t)n * Kd + kt * 32 + cq * 4);
        }
        cp_commit();
    };

    float c[4][NT][4];
#pragma unroll
    for (int mt = 0; mt < 4; mt++)
#pragma unroll
        for (int nt = 0; nt < NT; nt++)
#pragma unroll
            for (int i = 0; i < 4; i++) c[mt][nt][i] = 0.0f;

    load_tile(0, 0);
    for (int kt = 0; kt < KT; kt++) {
        int buf = kt & 1;
        if (kt + 1 < KT) { load_tile(kt + 1, buf ^ 1); cp_wait<1>(); }
        else             { cp_wait<0>(); }
        __syncthreads();
        const uint32_t* As = (const uint32_t*)(smem + buf * ABYTES);
        const uint32_t* Bs = (const uint32_t*)(smem + 2 * ABYTES + buf * BBYTES);
#pragma unroll
        for (int ks = 0; ks < 4; ks++) {
            uint32_t a[4][4], b[NT][2];
#pragma unroll
            for (int mt = 0; mt < 4; mt++) {
                int r = wm + mt * 16;
                a[mt][0] = As[(r + gid)     * STR + ks * 8 + tig];
                a[mt][1] = As[(r + gid + 8) * STR + ks * 8 + tig];
                a[mt][2] = As[(r + gid)     * STR + ks * 8 + tig + 4];
                a[mt][3] = As[(r + gid + 8) * STR + ks * 8 + tig + 4];
            }
#pragma unroll
            for (int nt = 0; nt < NT; nt++) {
                int n = wn + nt * 8 + gid;
                b[nt][0] = Bs[n * STR + ks * 8 + tig];
                b[nt][1] = Bs[n * STR + ks * 8 + tig + 4];
            }
#pragma unroll
            for (int mt = 0; mt < 4; mt++)
#pragma unroll
                for (int nt = 0; nt < NT; nt++)
                    asm volatile(
                        "mma.sync.aligned.m16n8k8.row.col.f32.tf32.tf32.f32 "
                        "{%0,%1,%2,%3}, {%4,%5,%6,%7}, {%8,%9}, {%0,%1,%2,%3};"
                        : "+f"(c[mt][nt][0]), "+f"(c[mt][nt][1]),
                          "+f"(c[mt][nt][2]), "+f"(c[mt][nt][3])
                        : "r"(a[mt][0]), "r"(a[mt][1]), "r"(a[mt][2]), "r"(a[mt][3]),
                          "r"(b[nt][0]), "r"(b[nt][1]));
        }
        __syncthreads();
    }

#pragma unroll
    for (int mt = 0; mt < 4; mt++)
#pragma unroll
        for (int nt = 0; nt < NT; nt++) {
            int col = wn + nt * 8 + tig * 2;
            int r0  = brow + wm + mt * 16 + gid;
            int r1  = r0 + 8;
            if (r0 < M)
                *(float2*)(C + (size_t)r0 * Nd + col) = make_float2(c[mt][nt][0], c[mt][nt][1]);
            if (r1 < M)
                *(float2*)(C + (size_t)r1 * Nd + col) = make_float2(c[mt][nt][2], c[mt][nt][3]);
        }
}

// ---------------- threefry2x32 key (0,42) ----------------
__device__ __forceinline__ void threefry_0_42(unsigned c0, unsigned c1,
                                              unsigned& o0, unsigned& o1) {
    const unsigned ks0 = 0u, ks1 = 42u, ks2 = 0u ^ 42u ^ 0x1BD11BDAu;
    unsigned x0 = c0 + ks0, x1 = c1 + ks1;
#define TF_RND(r) { x0 += x1; x1 = __funnelshift_l(x1, x1, (r)); x1 ^= x0; }
    TF_RND(13) TF_RND(15) TF_RND(26) TF_RND(6)
    x0 += ks1; x1 += ks2 + 1u;
    TF_RND(17) TF_RND(29) TF_RND(16) TF_RND(24)
    x0 += ks2; x1 += ks0 + 2u;
    TF_RND(13) TF_RND(15) TF_RND(26) TF_RND(6)
    x0 += ks0; x1 += ks1 + 3u;
    TF_RND(17) TF_RND(29) TF_RND(16) TF_RND(24)
    x0 += ks1; x1 += ks2 + 4u;
    TF_RND(13) TF_RND(15) TF_RND(26) TF_RND(6)
    x0 += ks2; x1 += ks0 + 5u;
#undef TF_RND
    o0 = x0; o1 = x1;
}
__device__ __forceinline__ float tf_uniform(unsigned i) {
    unsigned r0, r1;
    threefry_0_42(0u, i, r0, r1);
    unsigned bits = r0 ^ r1;
    return __uint_as_float((bits >> 9) | 0x3f800000u) - 1.0f;
}

// ---------------- layer1 pull-agg: agg1 = relu(Â h1 + b1) ∘ dropout -------
// 64 threads per node (one float4 column slice each); 4 nodes / 256-thr block.
__global__ void __launch_bounds__(256) k_agg1(const float* __restrict__ b1) {
    int g    = threadIdx.x >> 6;           // node slot in block
    int lane = threadIdx.x & 63;           // float4 column
    int node = blockIdx.x * 4 + g;
    if (node >= N_NODES) return;

    float dn = g_dinv[node];
    const float4* hrow = (const float4*)(g_h1 + (size_t)node * F_H);
    float4 acc = hrow[lane];
    float s = dn * dn;
    acc.x *= s; acc.y *= s; acc.z *= s; acc.w *= s;   // self loop

    int e0 = g_rowstart[node], e1 = g_rowstart[node + 1];
    for (int j = e0; j < e1; j++) {
        int src = g_csrc[j];                           // uniform within group
        float nrm = dn * g_dinv[src];
        float4 v = ((const float4*)(g_h1 + (size_t)src * F_H))[lane];
        acc.x = fmaf(nrm, v.x, acc.x);
        acc.y = fmaf(nrm, v.y, acc.y);
        acc.z = fmaf(nrm, v.z, acc.z);
        acc.w = fmaf(nrm, v.w, acc.w);
    }
    // bias + relu
    float4 bb = ((const float4*)b1)[lane];
    acc.x = fmaxf(acc.x + bb.x, 0.0f);
    acc.y = fmaxf(acc.y + bb.y, 0.0f);
    acc.z = fmaxf(acc.z + bb.z, 0.0f);
    acc.w = fmaxf(acc.w + bb.w, 0.0f);
    // dropout (JAX partitionable threefry, key (0,42))
    unsigned i0 = (unsigned)node * F_H + lane * 4;
    acc.x = (tf_uniform(i0 + 0) < 0.8f) ? acc.x * 1.25f : 0.0f;
    acc.y = (tf_uniform(i0 + 1) < 0.8f) ? acc.y * 1.25f : 0.0f;
    acc.z = (tf_uniform(i0 + 2) < 0.8f) ? acc.z * 1.25f : 0.0f;
    acc.w = (tf_uniform(i0 + 3) < 0.8f) ? acc.w * 1.25f : 0.0f;
    ((float4*)(g_agg1 + (size_t)node * F_H))[lane] = acc;
}

// ---------------- layer2 pull-agg + bias + softmax -> d_out ----------------
// One warp per node (32 lanes x float4 = 128 cols); 8 nodes / 256-thr block.
__global__ void __launch_bounds__(256) k_agg2(const float* __restrict__ b2,
                                              float* __restrict__ out) {
    int g    = threadIdx.x >> 5;
    int lane = threadIdx.x & 31;
    int node = blockIdx.x * 8 + g;
    if (node >= N_NODES) return;

    float dn = g_dinv[node];
    float4 acc = ((const float4*)(g_h2 + (size_t)node * F_OUT))[lane];
    float s = dn * dn;
    acc.x *= s; acc.y *= s; acc.z *= s; acc.w *= s;

    int e0 = g_rowstart[node], e1 = g_rowstart[node + 1];
    for (int j = e0; j < e1; j++) {
        int src = g_csrc[j];
        float nrm = dn * g_dinv[src];
        float4 v = ((const float4*)(g_h2 + (size_t)src * F_OUT))[lane];
        acc.x = fmaf(nrm, v.x, acc.x);
        acc.y = fmaf(nrm, v.y, acc.y);
        acc.z = fmaf(nrm, v.z, acc.z);
        acc.w = fmaf(nrm, v.w, acc.w);
    }
    float4 bb = ((const float4*)b2)[lane];
    acc.x += bb.x; acc.y += bb.y; acc.z += bb.z; acc.w += bb.w;

    float m = fmaxf(fmaxf(acc.x, acc.y), fmaxf(acc.z, acc.w));
#pragma unroll
    for (int off = 16; off > 0; off >>= 1)
        m = fmaxf(m, __shfl_xor_sync(0xffffffffu, m, off));
    acc.x = expf(acc.x - m); acc.y = expf(acc.y - m);
    acc.z = expf(acc.z - m); acc.w = expf(acc.w - m);
    float sum = acc.x + acc.y + acc.z + acc.w;
#pragma unroll
    for (int off = 16; off > 0; off >>= 1)
        sum += __shfl_xor_sync(0xffffffffu, sum, off);
    float inv = 1.0f / sum;
    acc.x *= inv; acc.y *= inv; acc.z *= inv; acc.w *= inv;
    ((float4*)(out + (size_t)node * F_OUT))[lane] = acc;
}

// ---------------- launcher ----------------
extern "C" void kernel_launch(void* const* d_in, const int* in_sizes, int n_in,
                              void* d_out, int out_size) {
    const float* x  = (const float*)d_in[0];
    const void*  ei = d_in[1];
    const float* W1 = (const float*)d_in[2];
    const float* b1 = (const float*)d_in[3];
    const float* W2 = (const float*)d_in[4];
    const float* b2 = (const float*)d_in[5];
    float* out = (float*)d_out;

    float* h1;   cudaGetSymbolAddress((void**)&h1,   g_h1);
    float* agg1; cudaGetSymbolAddress((void**)&agg1, g_agg1);
    float* h2;   cudaGetSymbolAddress((void**)&h2,   g_h2);
    uint32_t* w1t; cudaGetSymbolAddress((void**)&w1t, g_w1t);
    uint32_t* w2t; cudaGetSymbolAddress((void**)&w2t, g_w2t);

    constexpr int STRB = 36 * 4;
    constexpr int SMEM1 = 2 * 128 * STRB + 2 * F_H  * STRB;  // 110592
    constexpr int SMEM2 = 2 * 128 * STRB + 2 * F_OUT * STRB; // 73728
    cudaFuncSetAttribute(k_gemm_mma<F_IN, F_H>,
                         cudaFuncAttributeMaxDynamicSharedMemorySize, SMEM1);
    cudaFuncSetAttribute(k_gemm_mma<F_H, F_OUT>,
                         cudaFuncAttributeMaxDynamicSharedMemorySize, SMEM2);

    const int MTILES = (N_NODES + 127) / 128;  // 391

    // 0. dtype detect + degree/norm + CSR build + W prep
    k_detect<<<1, 1024>>>((const int*)ei);
    k_zero2<<<(N_NODES + 255) / 256, 256>>>();
    k_degree<<<(E_EDGES + 255) / 256, 256>>>(ei);
    k_dinv<<<(N_NODES + 255) / 256, 256>>>();
    k_scan<<<1, 1024>>>();
    k_fill<<<(E_EDGES + 255) / 256, 256>>>(ei);
    k_wprep<F_IN, F_H ><<<(F_IN * F_H  + 255) / 256, 256>>>(W1, w1t);
    k_wprep<F_H,  F_OUT><<<(F_H * F_OUT + 255) / 256, 256>>>(W2, w2t);

    // 1. h1 = x @ W1  (tf32 mma.sync, cp.async double-buffered)
    k_gemm_mma<F_IN, F_H><<<MTILES, 512, SMEM1>>>(x, w1t, h1, N_NODES);

    // 2. agg1 = dropout(relu(Â h1 + b1))  [CSR pull, fused]
    k_agg1<<<(N_NODES + 3) / 4, 256>>>(b1);

    // 3. h2 = agg1 @ W2
    k_gemm_mma<F_H, F_OUT><<<MTILES, 512, SMEM2>>>(agg1, w2t, h2, N_NODES);

    // 4. out = softmax(Â h2 + b2)  [CSR pull, fused]
    k_agg2<<<(N_NODES + 7) / 8, 256>>>(b2, out);
}

// round 8
// speedup vs baseline: 2.8099x; 1.2252x over previous
#include <cuda_runtime.h>
#include <cstdint>

// ---------------- problem constants ----------------
#define N_NODES 50000
#define F_IN    512
#define F_H     256
#define F_OUT   128
#define E_EDGES 800000
#define SCAN_B  1024
#define SCAN_NB ((N_NODES + SCAN_B - 1) / SCAN_B)   // 49

// ---------------- scratch (static device globals; no runtime alloc) --------
__device__ int   g_is64;
__device__ int   g_deg [N_NODES];
__device__ int   g_cursor[N_NODES];
__device__ int   g_rowstart[N_NODES + 1];
__device__ int   g_bsum[SCAN_NB];
__device__ int   g_csrc[E_EDGES];                    // src ids grouped by dst
__device__ float g_dinv[N_NODES];
__device__ float g_h1  [(size_t)N_NODES * F_H];
__device__ uint16_t g_h1b[(size_t)N_NODES * F_H];    // bf16 copy for gathers
__device__ float g_agg1[(size_t)N_NODES * F_H];
__device__ float g_h2  [(size_t)N_NODES * F_OUT];
__device__ uint16_t g_h2b[(size_t)N_NODES * F_OUT];  // bf16 copy for gathers
// W transposed to [N][K], tf32(rna) bit patterns
__device__ uint32_t g_w1t[F_IN * F_H];
__device__ uint32_t g_w2t[F_H * F_OUT];

// ---------------- helpers ----------------
__device__ __forceinline__ uint32_t f2tf32(float f) {
    uint32_t r; asm("cvt.rna.tf32.f32 %0, %1;" : "=r"(r) : "f"(f)); return r;
}
__device__ __forceinline__ uint32_t pack_bf16x2(float lo, float hi) {
    uint32_t r; asm("cvt.rn.bf16x2.f32 %0, %1, %2;" : "=r"(r) : "f"(hi), "f"(lo)); return r;
}
__device__ __forceinline__ float bf_lo(uint32_t u) { return __uint_as_float(u << 16); }
__device__ __forceinline__ float bf_hi(uint32_t u) { return __uint_as_float(u & 0xffff0000u); }
__device__ __forceinline__ uint32_t smem_u32(const void* p) {
    uint32_t a;
    asm("{ .reg .u64 t; cvta.to.shared.u64 t, %1; cvt.u32.u64 %0, t; }" : "=r"(a) : "l"(p));
    return a;
}
__device__ __forceinline__ void cp16(uint32_t s, const void* g) {
    asm volatile("cp.async.cg.shared.global [%0], [%1], 16;" :: "r"(s), "l"(g));
}
__device__ __forceinline__ void cp_commit() {
    asm volatile("cp.async.commit_group;" ::: "memory");
}
template <int N>
__device__ __forceinline__ void cp_wait() {
    asm volatile("cp.async.wait_group %0;" :: "n"(N) : "memory");
}

// ---------------- edge index access (int32 or int64) ----------------
__device__ __forceinline__ int edge_at(const void* ei, long long i) {
    if (g_is64) return (int)((const long long*)ei)[i];
    return ((const int*)ei)[i];
}
__global__ void k_detect(const int* ei32) {
    __shared__ int any_nonzero;
    if (threadIdx.x == 0) any_nonzero = 0;
    __syncthreads();
    if (ei32[2 * threadIdx.x + 1] != 0) atomicOr(&any_nonzero, 1);
    __syncthreads();
    if (threadIdx.x == 0) g_is64 = (any_nonzero == 0) ? 1 : 0;
}

// ---------------- degree / CSR ----------------
__global__ void k_zero2() {
    int i = blockIdx.x * blockDim.x + threadIdx.x;
    if (i < N_NODES) { g_deg[i] = 0; g_cursor[i] = 0; }
}
__global__ void k_degree(const void* ei) {
    int e = blockIdx.x * blockDim.x + threadIdx.x;
    if (e < E_EDGES) atomicAdd(&g_deg[edge_at(ei, (long long)E_EDGES + e)], 1);
}
// pass 1: per-block exclusive scan of deg -> rowstart (local), block total -> g_bsum.
// also computes dinv (fused).
__global__ void __launch_bounds__(SCAN_B) k_scan1() {
    __shared__ int ws[32];
    int i = blockIdx.x * SCAN_B + threadIdx.x;
    int lane = threadIdx.x & 31, warp = threadIdx.x >> 5;
    int v = (i < N_NODES) ? g_deg[i] : 0;
    if (i < N_NODES) g_dinv[i] = rsqrtf((float)(v + 1));
    int inc = v;
#pragma unroll
    for (int off = 1; off < 32; off <<= 1) {
        int y = __shfl_up_sync(0xffffffffu, inc, off);
        if (lane >= off) inc += y;
    }
    if (lane == 31) ws[warp] = inc;
    __syncthreads();
    if (warp == 0) {
        int s = ws[lane];
        int sinc = s;
#pragma unroll
        for (int off = 1; off < 32; off <<= 1) {
            int y = __shfl_up_sync(0xffffffffu, sinc, off);
            if (lane >= off) sinc += y;
        }
        ws[lane] = sinc - s;            // exclusive warp offsets
        if (lane == 31) g_bsum[blockIdx.x] = sinc;   // block total
    }
    __syncthreads();
    if (i < N_NODES) g_rowstart[i] = ws[warp] + inc - v;
}
// pass 2: exclusive scan of the SCAN_NB block sums (tiny)
__global__ void k_scan2() {
    __shared__ int s[SCAN_NB];
    if (threadIdx.x < SCAN_NB) s[threadIdx.x] = g_bsum[threadIdx.x];
    __syncthreads();
    if (threadIdx.x == 0) {
        int run = 0;
        for (int b = 0; b < SCAN_NB; b++) { int t = s[b]; s[b] = run; run += t; }
    }
    __syncthreads();
    if (threadIdx.x < SCAN_NB) g_bsum[threadIdx.x] = s[threadIdx.x];
}
// pass 3: add block offsets
__global__ void k_scan3() {
    int i = blockIdx.x * blockDim.x + threadIdx.x;
    if (i < N_NODES) g_rowstart[i] += g_bsum[i >> 10];
    if (i == 0) g_rowstart[N_NODES] = E_EDGES;
}
__global__ void k_fill(const void* ei) {
    int e = blockIdx.x * blockDim.x + threadIdx.x;
    if (e >= E_EDGES) return;
    int src = edge_at(ei, e);
    int dst = edge_at(ei, (long long)E_EDGES + e);
    int pos = g_rowstart[dst] + atomicAdd(&g_cursor[dst], 1);
    g_csrc[pos] = src;
}

// ---------------- W prep: transpose to [N][K], tf32(rna) ----------
template <int Kd, int Nd>
__global__ void k_wprep(const float* __restrict__ W, uint32_t* __restrict__ Wt) {
    int i = blockIdx.x * blockDim.x + threadIdx.x;
    if (i >= Kd * Nd) return;
    int k = i / Nd, n = i % Nd;
    Wt[(size_t)n * Kd + k] = f2tf32(W[i]);
}

// ---------------- tensor-core GEMM via mma.sync (tf32), cp.async x2 -------
// C[M,Nd] = A[M,Kd] * Bt[Nd,Kd]^T.  Also writes bf16 copy Cb.
template <int Kd, int Nd>
__global__ void __launch_bounds__(512) k_gemm_mma(const float* __restrict__ A,
                                                  const uint32_t* __restrict__ Bt,
                                                  float* __restrict__ C,
                                                  uint16_t* __restrict__ Cb, int M) {
    constexpr int WN  = Nd / 8;
    constexpr int NT  = WN / 8;
    constexpr int STR = 36;
    constexpr int ABYTES = 128 * STR * 4;
    constexpr int BBYTES = Nd * STR * 4;
    constexpr int KT = Kd / 32;
    extern __shared__ char smem[];
    const uint32_t sb = smem_u32(smem);

    const int t    = threadIdx.x;
    const int lane = t & 31, wid = t >> 5;
    const int gid  = lane >> 2, tig = lane & 3;
    const int wm   = (wid & 1) * 64;
    const int wn   = (wid >> 1) * WN;
    const int brow = blockIdx.x * 128;

    auto load_tile = [&](int kt, int buf) {
        uint32_t sA = sb + buf * ABYTES;
        uint32_t sB = sb + 2 * ABYTES + buf * BBYTES;
#pragma unroll
        for (int it = 0; it < 2; it++) {
            int f4 = it * 512 + t;
            int row = f4 >> 3, cq = f4 & 7;
            int grow = brow + row; if (grow > M - 1) grow = M - 1;
            cp16(sA + (uint32_t)(row * STR + cq * 4) * 4,
                 A + (size_t)grow * Kd + kt * 32 + cq * 4);
        }
#pragma unroll
        for (int it = 0; it < Nd / 64; it++) {
            int f4 = it * 512 + t;
            int n = f4 >> 3, cq = f4 & 7;
            cp16(sB + (uint32_t)(n * STR + cq * 4) * 4,
                 Bt + (size_t)n * Kd + kt * 32 + cq * 4);
        }
        cp_commit();
    };

    float c[4][NT][4];
#pragma unroll
    for (int mt = 0; mt < 4; mt++)
#pragma unroll
        for (int nt = 0; nt < NT; nt++)
#pragma unroll
            for (int i = 0; i < 4; i++) c[mt][nt][i] = 0.0f;

    load_tile(0, 0);
    for (int kt = 0; kt < KT; kt++) {
        int buf = kt & 1;
        if (kt + 1 < KT) { load_tile(kt + 1, buf ^ 1); cp_wait<1>(); }
        else             { cp_wait<0>(); }
        __syncthreads();
        const uint32_t* As = (const uint32_t*)(smem + buf * ABYTES);
        const uint32_t* Bs = (const uint32_t*)(smem + 2 * ABYTES + buf * BBYTES);
#pragma unroll
        for (int ks = 0; ks < 4; ks++) {
            uint32_t a[4][4], b[NT][2];
#pragma unroll
            for (int mt = 0; mt < 4; mt++) {
                int r = wm + mt * 16;
                a[mt][0] = As[(r + gid)     * STR + ks * 8 + tig];
                a[mt][1] = As[(r + gid + 8) * STR + ks * 8 + tig];
                a[mt][2] = As[(r + gid)     * STR + ks * 8 + tig + 4];
                a[mt][3] = As[(r + gid + 8) * STR + ks * 8 + tig + 4];
            }
#pragma unroll
            for (int nt = 0; nt < NT; nt++) {
                int n = wn + nt * 8 + gid;
                b[nt][0] = Bs[n * STR + ks * 8 + tig];
                b[nt][1] = Bs[n * STR + ks * 8 + tig + 4];
            }
#pragma unroll
            for (int mt = 0; mt < 4; mt++)
#pragma unroll
                for (int nt = 0; nt < NT; nt++)
                    asm volatile(
                        "mma.sync.aligned.m16n8k8.row.col.f32.tf32.tf32.f32 "
                        "{%0,%1,%2,%3}, {%4,%5,%6,%7}, {%8,%9}, {%0,%1,%2,%3};"
                        : "+f"(c[mt][nt][0]), "+f"(c[mt][nt][1]),
                          "+f"(c[mt][nt][2]), "+f"(c[mt][nt][3])
                        : "r"(a[mt][0]), "r"(a[mt][1]), "r"(a[mt][2]), "r"(a[mt][3]),
                          "r"(b[nt][0]), "r"(b[nt][1]));
        }
        __syncthreads();
    }

#pragma unroll
    for (int mt = 0; mt < 4; mt++)
#pragma unroll
        for (int nt = 0; nt < NT; nt++) {
            int col = wn + nt * 8 + tig * 2;
            int r0  = brow + wm + mt * 16 + gid;
            int r1  = r0 + 8;
            if (r0 < M) {
                *(float2*)(C + (size_t)r0 * Nd + col) = make_float2(c[mt][nt][0], c[mt][nt][1]);
                *(uint32_t*)(Cb + (size_t)r0 * Nd + col) = pack_bf16x2(c[mt][nt][0], c[mt][nt][1]);
            }
            if (r1 < M) {
                *(float2*)(C + (size_t)r1 * Nd + col) = make_float2(c[mt][nt][2], c[mt][nt][3]);
                *(uint32_t*)(Cb + (size_t)r1 * Nd + col) = pack_bf16x2(c[mt][nt][2], c[mt][nt][3]);
            }
        }
}

// ---------------- threefry2x32 key (0,42) ----------------
__device__ __forceinline__ void threefry_0_42(unsigned c0, unsigned c1,
                                              unsigned& o0, unsigned& o1) {
    const unsigned ks0 = 0u, ks1 = 42u, ks2 = 0u ^ 42u ^ 0x1BD11BDAu;
    unsigned x0 = c0 + ks0, x1 = c1 + ks1;
#define TF_RND(r) { x0 += x1; x1 = __funnelshift_l(x1, x1, (r)); x1 ^= x0; }
    TF_RND(13) TF_RND(15) TF_RND(26) TF_RND(6)
    x0 += ks1; x1 += ks2 + 1u;
    TF_RND(17) TF_RND(29) TF_RND(16) TF_RND(24)
    x0 += ks2; x1 += ks0 + 2u;
    TF_RND(13) TF_RND(15) TF_RND(26) TF_RND(6)
    x0 += ks0; x1 += ks1 + 3u;
    TF_RND(17) TF_RND(29) TF_RND(16) TF_RND(24)
    x0 += ks1; x1 += ks2 + 4u;
    TF_RND(13) TF_RND(15) TF_RND(26) TF_RND(6)
    x0 += ks2; x1 += ks0 + 5u;
#undef TF_RND
    o0 = x0; o1 = x1;
}
__device__ __forceinline__ float tf_uniform(unsigned i) {
    unsigned r0, r1;
    threefry_0_42(0u, i, r0, r1);
    unsigned bits = r0 ^ r1;
    return __uint_as_float((bits >> 9) | 0x3f800000u) - 1.0f;
}

// ---------------- layer1 pull-agg: agg1 = dropout(relu(Â h1 + b1)) ---------
// 32 threads per node, 8 cols each; gathers from bf16 copy; self term fp32.
__global__ void __launch_bounds__(256) k_agg1(const float* __restrict__ b1) {
    int g    = threadIdx.x >> 5;
    int lane = threadIdx.x & 31;
    int node = blockIdx.x * 8 + g;
    if (node >= N_NODES) return;

    float dn = g_dinv[node];
    float s = dn * dn;
    const float4* hf = (const float4*)(g_h1 + (size_t)node * F_H);
    float4 a0 = hf[lane * 2], a1 = hf[lane * 2 + 1];
    float acc[8] = {a0.x * s, a0.y * s, a0.z * s, a0.w * s,
                    a1.x * s, a1.y * s, a1.z * s, a1.w * s};

    int e0 = g_rowstart[node], e1 = g_rowstart[node + 1];
    for (int j = e0; j < e1; j++) {
        int src = g_csrc[j];
        float nrm = dn * g_dinv[src];
        uint4 r = ((const uint4*)(g_h1b + (size_t)src * F_H))[lane];  // 8 bf16
        acc[0] = fmaf(nrm, bf_lo(r.x), acc[0]);
        acc[1] = fmaf(nrm, bf_hi(r.x), acc[1]);
        acc[2] = fmaf(nrm, bf_lo(r.y), acc[2]);
        acc[3] = fmaf(nrm, bf_hi(r.y), acc[3]);
        acc[4] = fmaf(nrm, bf_lo(r.z), acc[4]);
        acc[5] = fmaf(nrm, bf_hi(r.z), acc[5]);
        acc[6] = fmaf(nrm, bf_lo(r.w), acc[6]);
        acc[7] = fmaf(nrm, bf_hi(r.w), acc[7]);
    }
    // bias + relu + dropout
    const float4 bb0 = ((const float4*)b1)[lane * 2];
    const float4 bb1 = ((const float4*)b1)[lane * 2 + 1];
    float bias[8] = {bb0.x, bb0.y, bb0.z, bb0.w, bb1.x, bb1.y, bb1.z, bb1.w};
    unsigned i0 = (unsigned)node * F_H + lane * 8;
    float outv[8];
#pragma unroll
    for (int q = 0; q < 8; q++) {
        float v = fmaxf(acc[q] + bias[q], 0.0f);
        outv[q] = (tf_uniform(i0 + q) < 0.8f) ? v * 1.25f : 0.0f;
    }
    float4* dst = (float4*)(g_agg1 + (size_t)node * F_H);
    dst[lane * 2]     = make_float4(outv[0], outv[1], outv[2], outv[3]);
    dst[lane * 2 + 1] = make_float4(outv[4], outv[5], outv[6], outv[7]);
}

// ---------------- layer2 pull-agg + bias + softmax -> d_out ----------------
// One warp per node; gathers from bf16 copy; self term fp32.
__global__ void __launch_bounds__(256) k_agg2(const float* __restrict__ b2,
                                              float* __restrict__ out) {
    int g    = threadIdx.x >> 5;
    int lane = threadIdx.x & 31;
    int node = blockIdx.x * 8 + g;
    if (node >= N_NODES) return;

    float dn = g_dinv[node];
    float4 acc = ((const float4*)(g_h2 + (size_t)node * F_OUT))[lane];
    float s = dn * dn;
    acc.x *= s; acc.y *= s; acc.z *= s; acc.w *= s;

    int e0 = g_rowstart[node], e1 = g_rowstart[node + 1];
    for (int j = e0; j < e1; j++) {
        int src = g_csrc[j];
        float nrm = dn * g_dinv[src];
        uint2 r = ((const uint2*)(g_h2b + (size_t)src * F_OUT))[lane];  // 4 bf16
        acc.x = fmaf(nrm, bf_lo(r.x), acc.x);
        acc.y = fmaf(nrm, bf_hi(r.x), acc.y);
        acc.z = fmaf(nrm, bf_lo(r.y), acc.z);
        acc.w = fmaf(nrm, bf_hi(r.y), acc.w);
    }
    float4 bb = ((const float4*)b2)[lane];
    acc.x += bb.x; acc.y += bb.y; acc.z += bb.z; acc.w += bb.w;

    float m = fmaxf(fmaxf(acc.x, acc.y), fmaxf(acc.z, acc.w));
#pragma unroll
    for (int off = 16; off > 0; off >>= 1)
        m = fmaxf(m, __shfl_xor_sync(0xffffffffu, m, off));
    acc.x = expf(acc.x - m); acc.y = expf(acc.y - m);
    acc.z = expf(acc.z - m); acc.w = expf(acc.w - m);
    float sum = acc.x + acc.y + acc.z + acc.w;
#pragma unroll
    for (int off = 16; off > 0; off >>= 1)
        sum += __shfl_xor_sync(0xffffffffu, sum, off);
    float inv = 1.0f / sum;
    acc.x *= inv; acc.y *= inv; acc.z *= inv; acc.w *= inv;
    ((float4*)(out + (size_t)node * F_OUT))[lane] = acc;
}

// ---------------- launcher ----------------
extern "C" void kernel_launch(void* const* d_in, const int* in_sizes, int n_in,
                              void* d_out, int out_size) {
    const float* x  = (const float*)d_in[0];
    const void*  ei = d_in[1];
    const float* W1 = (const float*)d_in[2];
    const float* b1 = (const float*)d_in[3];
    const float* W2 = (const float*)d_in[4];
    const float* b2 = (const float*)d_in[5];
    float* out = (float*)d_out;

    float* h1;   cudaGetSymbolAddress((void**)&h1,   g_h1);
    float* agg1; cudaGetSymbolAddress((void**)&agg1, g_agg1);
    float* h2;   cudaGetSymbolAddress((void**)&h2,   g_h2);
    uint16_t* h1b; cudaGetSymbolAddress((void**)&h1b, g_h1b);
    uint16_t* h2b; cudaGetSymbolAddress((void**)&h2b, g_h2b);
    uint32_t* w1t; cudaGetSymbolAddress((void**)&w1t, g_w1t);
    uint32_t* w2t; cudaGetSymbolAddress((void**)&w2t, g_w2t);

    constexpr int STRB = 36 * 4;
    constexpr int SMEM1 = 2 * 128 * STRB + 2 * F_H  * STRB;  // 110592
    constexpr int SMEM2 = 2 * 128 * STRB + 2 * F_OUT * STRB; // 73728
    cudaFuncSetAttribute(k_gemm_mma<F_IN, F_H>,
                         cudaFuncAttributeMaxDynamicSharedMemorySize, SMEM1);
    cudaFuncSetAttribute(k_gemm_mma<F_H, F_OUT>,
                         cudaFuncAttributeMaxDynamicSharedMemorySize, SMEM2);

    const int MTILES = (N_NODES + 127) / 128;  // 391

    // 0. dtype detect + degree + scan(3-pass, dinv fused) + fill + W prep
    k_detect<<<1, 1024>>>((const int*)ei);
    k_zero2<<<(N_NODES + 255) / 256, 256>>>();
    k_degree<<<(E_EDGES + 255) / 256, 256>>>(ei);
    k_scan1<<<SCAN_NB, SCAN_B>>>();
    k_scan2<<<1, 64>>>();
    k_scan3<<<(N_NODES + 255) / 256, 256>>>();
    k_fill<<<(E_EDGES + 255) / 256, 256>>>(ei);
    k_wprep<F_IN, F_H ><<<(F_IN * F_H  + 255) / 256, 256>>>(W1, w1t);
    k_wprep<F_H,  F_OUT><<<(F_H * F_OUT + 255) / 256, 256>>>(W2, w2t);

    // 1. h1 = x @ W1  (fp32 + bf16 copy)
    k_gemm_mma<F_IN, F_H><<<MTILES, 512, SMEM1>>>(x, w1t, h1, h1b, N_NODES);

    // 2. agg1 = dropout(relu(Â h1 + b1))  [CSR pull, bf16 gathers]
    k_agg1<<<(N_NODES + 7) / 8, 256>>>(b1);

    // 3. h2 = agg1 @ W2  (fp32 + bf16 copy)
    k_gemm_mma<F_H, F_OUT><<<MTILES, 512, SMEM2>>>(agg1, w2t, h2, h2b, N_NODES);

    // 4. out = softmax(Â h2 + b2)  [CSR pull, bf16 gathers]
    k_agg2<<<(N_NODES + 7) / 8, 256>>>(b2, out);
}

// round 10
// speedup vs baseline: 2.8969x; 1.0310x over previous
#include <cuda_runtime.h>
#include <cstdint>

// ---------------- problem constants ----------------
#define N_NODES 50000
#define F_IN    512
#define F_H     256
#define F_OUT   128
#define E_EDGES 800000
#define SCAN_B  1024
#define SCAN_NB ((N_NODES + SCAN_B - 1) / SCAN_B)   // 49

// ---------------- scratch (static device globals; no runtime alloc) --------
__device__ int   g_is64;
__device__ int   g_deg [N_NODES];
__device__ int   g_cursor[N_NODES];
__device__ int   g_rowstart[N_NODES + 1];
__device__ int   g_bsum[SCAN_NB];
__device__ int   g_csrc[E_EDGES];                    // src ids grouped by dst
__device__ float g_dinv[N_NODES];
__device__ float g_h1  [(size_t)N_NODES * F_H];
__device__ uint16_t g_h1b[(size_t)N_NODES * F_H];    // bf16 copy for gathers
__device__ float g_agg1[(size_t)N_NODES * F_H];
__device__ float g_h2  [(size_t)N_NODES * F_OUT];
__device__ uint16_t g_h2b[(size_t)N_NODES * F_OUT];  // bf16 copy for gathers
// W transposed to [N][K], tf32(rna) bit patterns
__device__ uint32_t g_w1t[F_IN * F_H];
__device__ uint32_t g_w2t[F_H * F_OUT];

// ---------------- helpers ----------------
__device__ __forceinline__ uint32_t f2tf32(float f) {
    uint32_t r; asm("cvt.rna.tf32.f32 %0, %1;" : "=r"(r) : "f"(f)); return r;
}
__device__ __forceinline__ uint32_t pack_bf16x2(float lo, float hi) {
    uint32_t r; asm("cvt.rn.bf16x2.f32 %0, %1, %2;" : "=r"(r) : "f"(hi), "f"(lo)); return r;
}
__device__ __forceinline__ float bf_lo(uint32_t u) { return __uint_as_float(u << 16); }
__device__ __forceinline__ float bf_hi(uint32_t u) { return __uint_as_float(u & 0xffff0000u); }
__device__ __forceinline__ uint32_t smem_u32(const void* p) {
    uint32_t a;
    asm("{ .reg .u64 t; cvta.to.shared.u64 t, %1; cvt.u32.u64 %0, t; }" : "=r"(a) : "l"(p));
    return a;
}
__device__ __forceinline__ void cp16(uint32_t s, const void* g) {
    asm volatile("cp.async.cg.shared.global [%0], [%1], 16;" :: "r"(s), "l"(g));
}
__device__ __forceinline__ void cp_commit() {
    asm volatile("cp.async.commit_group;" ::: "memory");
}
template <int N>
__device__ __forceinline__ void cp_wait() {
    asm volatile("cp.async.wait_group %0;" :: "n"(N) : "memory");
}

// ---------------- edge index access (int32 or int64) ----------------
__device__ __forceinline__ int edge_at(const void* ei, long long i) {
    if (g_is64) return (int)((const long long*)ei)[i];
    return ((const int*)ei)[i];
}
__global__ void k_detect(const int* ei32) {
    __shared__ int any_nonzero;
    if (threadIdx.x == 0) any_nonzero = 0;
    __syncthreads();
    if (ei32[2 * threadIdx.x + 1] != 0) atomicOr(&any_nonzero, 1);
    __syncthreads();
    if (threadIdx.x == 0) g_is64 = (any_nonzero == 0) ? 1 : 0;
}

// ---------------- degree / CSR ----------------
__global__ void k_zero() {
    int i = blockIdx.x * blockDim.x + threadIdx.x;
    if (i < N_NODES) g_deg[i] = 0;
}
__global__ void k_degree(const void* ei) {
    int e = blockIdx.x * blockDim.x + threadIdx.x;
    if (e < E_EDGES) atomicAdd(&g_deg[edge_at(ei, (long long)E_EDGES + e)], 1);
}
// pass 1: per-block exclusive scan of deg -> rowstart (local), block sums; dinv fused.
__global__ void __launch_bounds__(SCAN_B) k_scan1() {
    __shared__ int ws[32];
    int i = blockIdx.x * SCAN_B + threadIdx.x;
    int lane = threadIdx.x & 31, warp = threadIdx.x >> 5;
    int v = (i < N_NODES) ? g_deg[i] : 0;
    if (i < N_NODES) g_dinv[i] = rsqrtf((float)(v + 1));
    int inc = v;
#pragma unroll
    for (int off = 1; off < 32; off <<= 1) {
        int y = __shfl_up_sync(0xffffffffu, inc, off);
        if (lane >= off) inc += y;
    }
    if (lane == 31) ws[warp] = inc;
    __syncthreads();
    if (warp == 0) {
        int s = ws[lane];
        int sinc = s;
#pragma unroll
        for (int off = 1; off < 32; off <<= 1) {
            int y = __shfl_up_sync(0xffffffffu, sinc, off);
            if (lane >= off) sinc += y;
        }
        ws[lane] = sinc - s;
        if (lane == 31) g_bsum[blockIdx.x] = sinc;
    }
    __syncthreads();
    if (i < N_NODES) g_rowstart[i] = ws[warp] + inc - v;
}
__global__ void k_scan2() {
    __shared__ int s[SCAN_NB];
    if (threadIdx.x < SCAN_NB) s[threadIdx.x] = g_bsum[threadIdx.x];
    __syncthreads();
    if (threadIdx.x == 0) {
        int run = 0;
        for (int b = 0; b < SCAN_NB; b++) { int t = s[b]; s[b] = run; run += t; }
    }
    __syncthreads();
    if (threadIdx.x < SCAN_NB) g_bsum[threadIdx.x] = s[threadIdx.x];
}
// pass 3: add block offsets; also init fill cursors to rowstart.
__global__ void k_scan3() {
    int i = blockIdx.x * blockDim.x + threadIdx.x;
    if (i < N_NODES) {
        int rs = g_rowstart[i] + g_bsum[i >> 10];
        g_rowstart[i] = rs;
        g_cursor[i]   = rs;
    }
    if (i == 0) g_rowstart[N_NODES] = E_EDGES;
}
__global__ void k_fill(const void* ei) {
    int e = blockIdx.x * blockDim.x + threadIdx.x;
    if (e >= E_EDGES) return;
    int src = edge_at(ei, e);
    int dst = edge_at(ei, (long long)E_EDGES + e);
    int pos = atomicAdd(&g_cursor[dst], 1);
    g_csrc[pos] = src;
}

// ---------------- W prep: transpose to [N][K], tf32(rna) ----------
template <int Kd, int Nd>
__global__ void k_wprep(const float* __restrict__ W, uint32_t* __restrict__ Wt) {
    int i = blockIdx.x * blockDim.x + threadIdx.x;
    if (i >= Kd * Nd) return;
    int k = i / Nd, n = i % Nd;
    Wt[(size_t)n * Kd + k] = f2tf32(W[i]);
}

// ---------------- tensor-core GEMM via mma.sync (tf32), cp.async x3 -------
// C[M,Nd] = A[M,Kd] * Bt[Nd,Kd]^T.  Also writes bf16 copy Cb.
template <int Kd, int Nd>
__global__ void __launch_bounds__(512) k_gemm_mma(const float* __restrict__ A,
                                                  const uint32_t* __restrict__ Bt,
                                                  float* __restrict__ C,
                                                  uint16_t* __restrict__ Cb, int M) {
    constexpr int WN  = Nd / 8;
    constexpr int NT  = WN / 8;
    constexpr int STR = 36;
    constexpr int ABYTES = 128 * STR * 4;
    constexpr int BBYTES = Nd * STR * 4;
    constexpr int KT = Kd / 32;
    extern __shared__ char smem[];
    const uint32_t sb = smem_u32(smem);

    const int t    = threadIdx.x;
    const int lane = t & 31, wid = t >> 5;
    const int gid  = lane >> 2, tig = lane & 3;
    const int wm   = (wid & 1) * 64;
    const int wn   = (wid >> 1) * WN;
    const int brow = blockIdx.x * 128;

    auto load_tile = [&](int kt, int buf) {
        uint32_t sA = sb + buf * ABYTES;
        uint32_t sB = sb + 3 * ABYTES + buf * BBYTES;
#pragma unroll
        for (int it = 0; it < 2; it++) {
            int f4 = it * 512 + t;
            int row = f4 >> 3, cq = f4 & 7;
            int grow = brow + row; if (grow > M - 1) grow = M - 1;
            cp16(sA + (uint32_t)(row * STR + cq * 4) * 4,
                 A + (size_t)grow * Kd + kt * 32 + cq * 4);
        }
#pragma unroll
        for (int it = 0; it < Nd / 64; it++) {
            int f4 = it * 512 + t;
            int n = f4 >> 3, cq = f4 & 7;
            cp16(sB + (uint32_t)(n * STR + cq * 4) * 4,
                 Bt + (size_t)n * Kd + kt * 32 + cq * 4);
        }
        cp_commit();
    };

    float c[4][NT][4];
#pragma unroll
    for (int mt = 0; mt < 4; mt++)
#pragma unroll
        for (int nt = 0; nt < NT; nt++)
#pragma unroll
            for (int i = 0; i < 4; i++) c[mt][nt][i] = 0.0f;

    load_tile(0, 0);
    load_tile(1, 1);
    for (int kt = 0; kt < KT; kt++) {
        int buf = kt % 3;
        if (kt + 2 < KT) { load_tile(kt + 2, (kt + 2) % 3); cp_wait<2>(); }
        else if (kt + 1 < KT) { cp_wait<1>(); }
        else { cp_wait<0>(); }
        __syncthreads();
        const uint32_t* As = (const uint32_t*)(smem + buf * ABYTES);
        const uint32_t* Bs = (const uint32_t*)(smem + 3 * ABYTES + buf * BBYTES);
#pragma unroll
        for (int ks = 0; ks < 4; ks++) {
            uint32_t a[4][4], b[NT][2];
#pragma unroll
            for (int mt = 0; mt < 4; mt++) {
                int r = wm + mt * 16;
                a[mt][0] = As[(r + gid)     * STR + ks * 8 + tig];
                a[mt][1] = As[(r + gid + 8) * STR + ks * 8 + tig];
                a[mt][2] = As[(r + gid)     * STR + ks * 8 + tig + 4];
                a[mt][3] = As[(r + gid + 8) * STR + ks * 8 + tig + 4];
            }
#pragma unroll
            for (int nt = 0; nt < NT; nt++) {
                int n = wn + nt * 8 + gid;
                b[nt][0] = Bs[n * STR + ks * 8 + tig];
                b[nt][1] = Bs[n * STR + ks * 8 + tig + 4];
            }
#pragma unroll
            for (int mt = 0; mt < 4; mt++)
#pragma unroll
                for (int nt = 0; nt < NT; nt++)
                    asm volatile(
                        "mma.sync.aligned.m16n8k8.row.col.f32.tf32.tf32.f32 "
                        "{%0,%1,%2,%3}, {%4,%5,%6,%7}, {%8,%9}, {%0,%1,%2,%3};"
                        : "+f"(c[mt][nt][0]), "+f"(c[mt][nt][1]),
                          "+f"(c[mt][nt][2]), "+f"(c[mt][nt][3])
                        : "r"(a[mt][0]), "r"(a[mt][1]), "r"(a[mt][2]), "r"(a[mt][3]),
                          "r"(b[nt][0]), "r"(b[nt][1]));
        }
        __syncthreads();
    }

#pragma unroll
    for (int mt = 0; mt < 4; mt++)
#pragma unroll
        for (int nt = 0; nt < NT; nt++) {
            int col = wn + nt * 8 + tig * 2;
            int r0  = brow + wm + mt * 16 + gid;
            int r1  = r0 + 8;
            if (r0 < M) {
                *(float2*)(C + (size_t)r0 * Nd + col) = make_float2(c[mt][nt][0], c[mt][nt][1]);
                *(uint32_t*)(Cb + (size_t)r0 * Nd + col) = pack_bf16x2(c[mt][nt][0], c[mt][nt][1]);
            }
            if (r1 < M) {
                *(float2*)(C + (size_t)r1 * Nd + col) = make_float2(c[mt][nt][2], c[mt][nt][3]);
                *(uint32_t*)(Cb + (size_t)r1 * Nd + col) = pack_bf16x2(c[mt][nt][2], c[mt][nt][3]);
            }
        }
}

// ---------------- threefry2x32 key (0,42) ----------------
__device__ __forceinline__ void threefry_0_42(unsigned c0, unsigned c1,
                                              unsigned& o0, unsigned& o1) {
    const unsigned ks0 = 0u, ks1 = 42u, ks2 = 0u ^ 42u ^ 0x1BD11BDAu;
    unsigned x0 = c0 + ks0, x1 = c1 + ks1;
#define TF_RND(r) { x0 += x1; x1 = __funnelshift_l(x1, x1, (r)); x1 ^= x0; }
    TF_RND(13) TF_RND(15) TF_RND(26) TF_RND(6)
    x0 += ks1; x1 += ks2 + 1u;
    TF_RND(17) TF_RND(29) TF_RND(16) TF_RND(24)
    x0 += ks2; x1 += ks0 + 2u;
    TF_RND(13) TF_RND(15) TF_RND(26) TF_RND(6)
    x0 += ks0; x1 += ks1 + 3u;
    TF_RND(17) TF_RND(29) TF_RND(16) TF_RND(24)
    x0 += ks1; x1 += ks2 + 4u;
    TF_RND(13) TF_RND(15) TF_RND(26) TF_RND(6)
    x0 += ks2; x1 += ks0 + 5u;
#undef TF_RND
    o0 = x0; o1 = x1;
}
__device__ __forceinline__ float tf_uniform(unsigned i) {
    unsigned r0, r1;
    threefry_0_42(0u, i, r0, r1);
    unsigned bits = r0 ^ r1;
    return __uint_as_float((bits >> 9) | 0x3f800000u) - 1.0f;
}

// ---------------- layer1 pull-agg: agg1 = dropout(relu(Â h1 + b1)) ---------
// 32 threads per node, 8 cols each; bf16 gathers, 2-edge unroll for MLP.
__global__ void __launch_bounds__(256) k_agg1(const float* __restrict__ b1) {
    int g    = threadIdx.x >> 5;
    int lane = threadIdx.x & 31;
    int node = blockIdx.x * 8 + g;
    if (node >= N_NODES) return;

    float dn = g_dinv[node];
    float s = dn * dn;
    const float4* hf = (const float4*)(g_h1 + (size_t)node * F_H);
    float4 a0 = hf[lane * 2], a1 = hf[lane * 2 + 1];
    float acc[8] = {a0.x * s, a0.y * s, a0.z * s, a0.w * s,
                    a1.x * s, a1.y * s, a1.z * s, a1.w * s};

    int e0 = g_rowstart[node], e1 = g_rowstart[node + 1];
    int j = e0;
    for (; j + 2 <= e1; j += 2) {
        int s0 = g_csrc[j], s1 = g_csrc[j + 1];
        float n0 = dn * g_dinv[s0], n1 = dn * g_dinv[s1];
        uint4 r0 = ((const uint4*)(g_h1b + (size_t)s0 * F_H))[lane];
        uint4 r1 = ((const uint4*)(g_h1b + (size_t)s1 * F_H))[lane];
        acc[0] = fmaf(n0, bf_lo(r0.x), acc[0]); acc[1] = fmaf(n0, bf_hi(r0.x), acc[1]);
        acc[2] = fmaf(n0, bf_lo(r0.y), acc[2]); acc[3] = fmaf(n0, bf_hi(r0.y), acc[3]);
        acc[4] = fmaf(n0, bf_lo(r0.z), acc[4]); acc[5] = fmaf(n0, bf_hi(r0.z), acc[5]);
        acc[6] = fmaf(n0, bf_lo(r0.w), acc[6]); acc[7] = fmaf(n0, bf_hi(r0.w), acc[7]);
        acc[0] = fmaf(n1, bf_lo(r1.x), acc[0]); acc[1] = fmaf(n1, bf_hi(r1.x), acc[1]);
        acc[2] = fmaf(n1, bf_lo(r1.y), acc[2]); acc[3] = fmaf(n1, bf_hi(r1.y), acc[3]);
        acc[4] = fmaf(n1, bf_lo(r1.z), acc[4]); acc[5] = fmaf(n1, bf_hi(r1.z), acc[5]);
        acc[6] = fmaf(n1, bf_lo(r1.w), acc[6]); acc[7] = fmaf(n1, bf_hi(r1.w), acc[7]);
    }
    if (j < e1) {
        int s0 = g_csrc[j];
        float n0 = dn * g_dinv[s0];
        uint4 r0 = ((const uint4*)(g_h1b + (size_t)s0 * F_H))[lane];
        acc[0] = fmaf(n0, bf_lo(r0.x), acc[0]); acc[1] = fmaf(n0, bf_hi(r0.x), acc[1]);
        acc[2] = fmaf(n0, bf_lo(r0.y), acc[2]); acc[3] = fmaf(n0, bf_hi(r0.y), acc[3]);
        acc[4] = fmaf(n0, bf_lo(r0.z), acc[4]); acc[5] = fmaf(n0, bf_hi(r0.z), acc[5]);
        acc[6] = fmaf(n0, bf_lo(r0.w), acc[6]); acc[7] = fmaf(n0, bf_hi(r0.w), acc[7]);
    }
    const float4 bb0 = ((const float4*)b1)[lane * 2];
    const float4 bb1 = ((const float4*)b1)[lane * 2 + 1];
    float bias[8] = {bb0.x, bb0.y, bb0.z, bb0.w, bb1.x, bb1.y, bb1.z, bb1.w};
    unsigned i0 = (unsigned)node * F_H + lane * 8;
    float outv[8];
#pragma unroll
    for (int q = 0; q < 8; q++) {
        float v = fmaxf(acc[q] + bias[q], 0.0f);
        outv[q] = (tf_uniform(i0 + q) < 0.8f) ? v * 1.25f : 0.0f;
    }
    float4* dst = (float4*)(g_agg1 + (size_t)node * F_H);
    dst[lane * 2]     = make_float4(outv[0], outv[1], outv[2], outv[3]);
    dst[lane * 2 + 1] = make_float4(outv[4], outv[5], outv[6], outv[7]);
}

// ---------------- layer2 pull-agg + bias + softmax -> d_out ----------------
__global__ void __launch_bounds__(256) k_agg2(const float* __restrict__ b2,
                                              float* __restrict__ out) {
    int g    = threadIdx.x >> 5;
    int lane = threadIdx.x & 31;
    int node = blockIdx.x * 8 + g;
    if (node >= N_NODES) return;

    float dn = g_dinv[node];
    float4 acc = ((const float4*)(g_h2 + (size_t)node * F_OUT))[lane];
    float s = dn * dn;
    acc.x *= s; acc.y *= s; acc.z *= s; acc.w *= s;

    int e0 = g_rowstart[node], e1 = g_rowstart[node + 1];
    int j = e0;
    for (; j + 2 <= e1; j += 2) {
        int s0 = g_csrc[j], s1 = g_csrc[j + 1];
        float n0 = dn * g_dinv[s0], n1 = dn * g_dinv[s1];
        uint2 r0 = ((const uint2*)(g_h2b + (size_t)s0 * F_OUT))[lane];
        uint2 r1 = ((const uint2*)(g_h2b + (size_t)s1 * F_OUT))[lane];
        acc.x = fmaf(n0, bf_lo(r0.x), acc.x); acc.y = fmaf(n0, bf_hi(r0.x), acc.y);
        acc.z = fmaf(n0, bf_lo(r0.y), acc.z); acc.w = fmaf(n0, bf_hi(r0.y), acc.w);
        acc.x = fmaf(n1, bf_lo(r1.x), acc.x); acc.y = fmaf(n1, bf_hi(r1.x), acc.y);
        acc.z = fmaf(n1, bf_lo(r1.y), acc.z); acc.w = fmaf(n1, bf_hi(r1.y), acc.w);
    }
    if (j < e1) {
        int s0 = g_csrc[j];
        float n0 = dn * g_dinv[s0];
        uint2 r0 = ((const uint2*)(g_h2b + (size_t)s0 * F_OUT))[lane];
        acc.x = fmaf(n0, bf_lo(r0.x), acc.x); acc.y = fmaf(n0, bf_hi(r0.x), acc.y);
        acc.z = fmaf(n0, bf_lo(r0.y), acc.z); acc.w = fmaf(n0, bf_hi(r0.y), acc.w);
    }
    float4 bb = ((const float4*)b2)[lane];
    acc.x += bb.x; acc.y += bb.y; acc.z += bb.z; acc.w += bb.w;

    float m = fmaxf(fmaxf(acc.x, acc.y), fmaxf(acc.z, acc.w));
#pragma unroll
    for (int off = 16; off > 0; off >>= 1)
        m = fmaxf(m, __shfl_xor_sync(0xffffffffu, m, off));
    acc.x = expf(acc.x - m); acc.y = expf(acc.y - m);
    acc.z = expf(acc.z - m); acc.w = expf(acc.w - m);
    float sum = acc.x + acc.y + acc.z + acc.w;
#pragma unroll
    for (int off = 16; off > 0; off >>= 1)
        sum += __shfl_xor_sync(0xffffffffu, sum, off);
    float inv = 1.0f / sum;
    acc.x *= inv; acc.y *= inv; acc.z *= inv; acc.w *= inv;
    ((float4*)(out + (size_t)node * F_OUT))[lane] = acc;
}

// ---------------- launcher ----------------
extern "C" void kernel_launch(void* const* d_in, const int* in_sizes, int n_in,
                              void* d_out, int out_size) {
    const float* x  = (const float*)d_in[0];
    const void*  ei = d_in[1];
    const float* W1 = (const float*)d_in[2];
    const float* b1 = (const float*)d_in[3];
    const float* W2 = (const float*)d_in[4];
    const float* b2 = (const float*)d_in[5];
    float* out = (float*)d_out;

    float* h1;   cudaGetSymbolAddress((void**)&h1,   g_h1);
    float* agg1; cudaGetSymbolAddress((void**)&agg1, g_agg1);
    float* h2;   cudaGetSymbolAddress((void**)&h2,   g_h2);
    uint16_t* h1b; cudaGetSymbolAddress((void**)&h1b, g_h1b);
    uint16_t* h2b; cudaGetSymbolAddress((void**)&h2b, g_h2b);
    uint32_t* w1t; cudaGetSymbolAddress((void**)&w1t, g_w1t);
    uint32_t* w2t; cudaGetSymbolAddress((void**)&w2t, g_w2t);

    constexpr int STRB = 36 * 4;
    constexpr int SMEM1 = 3 * 128 * STRB + 3 * F_H  * STRB;  // 165888
    constexpr int SMEM2 = 3 * 128 * STRB + 3 * F_OUT * STRB; // 110592
    cudaFuncSetAttribute(k_gemm_mma<F_IN, F_H>,
                         cudaFuncAttributeMaxDynamicSharedMemorySize, SMEM1);
    cudaFuncSetAttribute(k_gemm_mma<F_H, F_OUT>,
                         cudaFuncAttributeMaxDynamicSharedMemorySize, SMEM2);

    const int MTILES = (N_NODES + 127) / 128;  // 391

    // launch order puts GEMM1 at index 5 (ncu -s 5 profiles it).
    k_detect<<<1, 1024>>>((const int*)ei);                                   // 0
    k_zero<<<(N_NODES + 255) / 256, 256>>>();                                // 1
    k_degree<<<(E_EDGES + 255) / 256, 256>>>(ei);                            // 2
    k_wprep<F_IN, F_H ><<<(F_IN * F_H  + 255) / 256, 256>>>(W1, w1t);        // 3
    k_wprep<F_H,  F_OUT><<<(F_H * F_OUT + 255) / 256, 256>>>(W2, w2t);       // 4
    k_gemm_mma<F_IN, F_H><<<MTILES, 512, SMEM1>>>(x, w1t, h1, h1b, N_NODES); // 5 <- profiled
    k_scan1<<<SCAN_NB, SCAN_B>>>();                                          // 6
    k_scan2<<<1, 64>>>();                                                    // 7
    k_scan3<<<(N_NODES + 255) / 256, 256>>>();                               // 8
    k_fill<<<(E_EDGES + 255) / 256, 256>>>(ei);                              // 9
    k_agg1<<<(N_NODES + 7) / 8, 256>>>(b1);                                  // 10
    k_gemm_mma<F_H, F_OUT><<<MTILES, 512, SMEM2>>>(agg1, w2t, h2, h2b, N_NODES); // 11
    k_agg2<<<(N_NODES + 7) / 8, 256>>>(b2, out);                             // 12
}

// round 11
// speedup vs baseline: 3.1230x; 1.0781x over previous
#include <cuda_runtime.h>
#include <cstdint>

// ---------------- problem constants ----------------
#define N_NODES 50000
#define F_IN    512
#define F_H     256
#define F_OUT   128
#define E_EDGES 800000
#define SCAN_B  1024
#define SCAN_NB ((N_NODES + SCAN_B - 1) / SCAN_B)   // 49

// ---------------- scratch (static device globals; no runtime alloc) --------
__device__ int   g_is64;
__device__ int   g_deg [N_NODES];
__device__ int   g_cursor[N_NODES];
__device__ int   g_rowstart[N_NODES + 1];
__device__ int   g_bsum[SCAN_NB];
__device__ int   g_csrc[E_EDGES];                    // src ids grouped by dst
__device__ float g_dinv[N_NODES];
__device__ float g_h1  [(size_t)N_NODES * F_H];
__device__ uint16_t g_h1b[(size_t)N_NODES * F_H];    // bf16 copy for gathers
__device__ float g_agg1[(size_t)N_NODES * F_H];
__device__ float g_h2  [(size_t)N_NODES * F_OUT];
__device__ uint16_t g_h2b[(size_t)N_NODES * F_OUT];  // bf16 copy for gathers
// W transposed to [N][K], tf32(rna) bit patterns
__device__ uint32_t g_w1t[F_IN * F_H];
__device__ uint32_t g_w2t[F_H * F_OUT];

// ---------------- helpers ----------------
__device__ __forceinline__ uint32_t f2tf32(float f) {
    uint32_t r; asm("cvt.rna.tf32.f32 %0, %1;" : "=r"(r) : "f"(f)); return r;
}
__device__ __forceinline__ uint32_t pack_bf16x2(float lo, float hi) {
    uint32_t r; asm("cvt.rn.bf16x2.f32 %0, %1, %2;" : "=r"(r) : "f"(hi), "f"(lo)); return r;
}
__device__ __forceinline__ float bf_lo(uint32_t u) { return __uint_as_float(u << 16); }
__device__ __forceinline__ float bf_hi(uint32_t u) { return __uint_as_float(u & 0xffff0000u); }
__device__ __forceinline__ uint32_t smem_u32(const void* p) {
    uint32_t a;
    asm("{ .reg .u64 t; cvta.to.shared.u64 t, %1; cvt.u32.u64 %0, t; }" : "=r"(a) : "l"(p));
    return a;
}
__device__ __forceinline__ void cp16(uint32_t s, const void* g) {
    asm volatile("cp.async.cg.shared.global [%0], [%1], 16;" :: "r"(s), "l"(g));
}
__device__ __forceinline__ void cp_commit() {
    asm volatile("cp.async.commit_group;" ::: "memory");
}
template <int N>
__device__ __forceinline__ void cp_wait() {
    asm volatile("cp.async.wait_group %0;" :: "n"(N) : "memory");
}

// ---------------- edge index access (int32 or int64) ----------------
__device__ __forceinline__ int edge_at(const void* ei, long long i) {
    if (g_is64) return (int)((const long long*)ei)[i];
    return ((const int*)ei)[i];
}
__global__ void k_detect(const int* ei32) {
    __shared__ int any_nonzero;
    if (threadIdx.x == 0) any_nonzero = 0;
    __syncthreads();
    if (ei32[2 * threadIdx.x + 1] != 0) atomicOr(&any_nonzero, 1);
    __syncthreads();
    if (threadIdx.x == 0) g_is64 = (any_nonzero == 0) ? 1 : 0;
}

// ---------------- degree / CSR ----------------
__global__ void k_zero() {
    int i = blockIdx.x * blockDim.x + threadIdx.x;
    if (i < N_NODES) g_deg[i] = 0;
}
__global__ void k_degree(const void* ei) {
    int e = blockIdx.x * blockDim.x + threadIdx.x;
    if (e < E_EDGES) atomicAdd(&g_deg[edge_at(ei, (long long)E_EDGES + e)], 1);
}
// pass 1: per-block exclusive scan of deg -> rowstart (local), block sums; dinv fused.
__global__ void __launch_bounds__(SCAN_B) k_scan1() {
    __shared__ int ws[32];
    int i = blockIdx.x * SCAN_B + threadIdx.x;
    int lane = threadIdx.x & 31, warp = threadIdx.x >> 5;
    int v = (i < N_NODES) ? g_deg[i] : 0;
    if (i < N_NODES) g_dinv[i] = rsqrtf((float)(v + 1));
    int inc = v;
#pragma unroll
    for (int off = 1; off < 32; off <<= 1) {
        int y = __shfl_up_sync(0xffffffffu, inc, off);
        if (lane >= off) inc += y;
    }
    if (lane == 31) ws[warp] = inc;
    __syncthreads();
    if (warp == 0) {
        int s = ws[lane];
        int sinc = s;
#pragma unroll
        for (int off = 1; off < 32; off <<= 1) {
            int y = __shfl_up_sync(0xffffffffu, sinc, off);
            if (lane >= off) sinc += y;
        }
        ws[lane] = sinc - s;
        if (lane == 31) g_bsum[blockIdx.x] = sinc;
    }
    __syncthreads();
    if (i < N_NODES) g_rowstart[i] = ws[warp] + inc - v;
}
__global__ void k_scan2() {
    __shared__ int s[SCAN_NB];
    if (threadIdx.x < SCAN_NB) s[threadIdx.x] = g_bsum[threadIdx.x];
    __syncthreads();
    if (threadIdx.x == 0) {
        int run = 0;
        for (int b = 0; b < SCAN_NB; b++) { int t = s[b]; s[b] = run; run += t; }
    }
    __syncthreads();
    if (threadIdx.x < SCAN_NB) g_bsum[threadIdx.x] = s[threadIdx.x];
}
// pass 3: add block offsets; also init fill cursors to rowstart.
__global__ void k_scan3() {
    int i = blockIdx.x * blockDim.x + threadIdx.x;
    if (i < N_NODES) {
        int rs = g_rowstart[i] + g_bsum[i >> 10];
        g_rowstart[i] = rs;
        g_cursor[i]   = rs;
    }
    if (i == 0) g_rowstart[N_NODES] = E_EDGES;
}
__global__ void k_fill(const void* ei) {
    int e = blockIdx.x * blockDim.x + threadIdx.x;
    if (e >= E_EDGES) return;
    int src = edge_at(ei, e);
    int dst = edge_at(ei, (long long)E_EDGES + e);
    int pos = atomicAdd(&g_cursor[dst], 1);
    g_csrc[pos] = src;
}

// ---------------- W prep: transpose to [N][K], tf32(rna) ----------
template <int Kd, int Nd>
__global__ void k_wprep(const float* __restrict__ W, uint32_t* __restrict__ Wt) {
    int i = blockIdx.x * blockDim.x + threadIdx.x;
    if (i >= Kd * Nd) return;
    int k = i / Nd, n = i % Nd;
    Wt[(size_t)n * Kd + k] = f2tf32(W[i]);
}

// ---------------- tensor-core GEMM via mma.sync (tf32), cp.async x3 -------
// C[M,Nd] = A[M,Kd] * Bt[Nd,Kd]^T.  Also writes bf16 copy Cb.
template <int Kd, int Nd>
__global__ void __launch_bounds__(512) k_gemm_mma(const float* __restrict__ A,
                                                  const uint32_t* __restrict__ Bt,
                                                  float* __restrict__ C,
                                                  uint16_t* __restrict__ Cb, int M) {
    constexpr int WN  = Nd / 8;
    constexpr int NT  = WN / 8;
    constexpr int STR = 36;
    constexpr int ABYTES = 128 * STR * 4;
    constexpr int BBYTES = Nd * STR * 4;
    constexpr int KT = Kd / 32;
    extern __shared__ char smem[];
    const uint32_t sb = smem_u32(smem);

    const int t    = threadIdx.x;
    const int lane = t & 31, wid = t >> 5;
    const int gid  = lane >> 2, tig = lane & 3;
    const int wm   = (wid & 1) * 64;
    const int wn   = (wid >> 1) * WN;
    const int brow = blockIdx.x * 128;

    auto load_tile = [&](int kt, int buf) {
        uint32_t sA = sb + buf * ABYTES;
        uint32_t sB = sb + 3 * ABYTES + buf * BBYTES;
#pragma unroll
        for (int it = 0; it < 2; it++) {
            int f4 = it * 512 + t;
            int row = f4 >> 3, cq = f4 & 7;
            int grow = brow + row; if (grow > M - 1) grow = M - 1;
            cp16(sA + (uint32_t)(row * STR + cq * 4) * 4,
                 A + (size_t)grow * Kd + kt * 32 + cq * 4);
        }
#pragma unroll
        for (int it = 0; it < Nd / 64; it++) {
            int f4 = it * 512 + t;
            int n = f4 >> 3, cq = f4 & 7;
            cp16(sB + (uint32_t)(n * STR + cq * 4) * 4,
                 Bt + (size_t)n * Kd + kt * 32 + cq * 4);
        }
        cp_commit();
    };

    float c[4][NT][4];
#pragma unroll
    for (int mt = 0; mt < 4; mt++)
#pragma unroll
        for (int nt = 0; nt < NT; nt++)
#pragma unroll
            for (int i = 0; i < 4; i++) c[mt][nt][i] = 0.0f;

    load_tile(0, 0);
    load_tile(1, 1);
    for (int kt = 0; kt < KT; kt++) {
        int buf = kt % 3;
        if (kt + 2 < KT) { load_tile(kt + 2, (kt + 2) % 3); cp_wait<2>(); }
        else if (kt + 1 < KT) { cp_wait<1>(); }
        else { cp_wait<0>(); }
        __syncthreads();
        const uint32_t* As = (const uint32_t*)(smem + buf * ABYTES);
        const uint32_t* Bs = (const uint32_t*)(smem + 3 * ABYTES + buf * BBYTES);
#pragma unroll
        for (int ks = 0; ks < 4; ks++) {
            uint32_t a[4][4], b[NT][2];
#pragma unroll
            for (int mt = 0; mt < 4; mt++) {
                int r = wm + mt * 16;
                a[mt][0] = As[(r + gid)     * STR + ks * 8 + tig];
                a[mt][1] = As[(r + gid + 8) * STR + ks * 8 + tig];
                a[mt][2] = As[(r + gid)     * STR + ks * 8 + tig + 4];
                a[mt][3] = As[(r + gid + 8) * STR + ks * 8 + tig + 4];
            }
#pragma unroll
            for (int nt = 0; nt < NT; nt++) {
                int n = wn + nt * 8 + gid;
                b[nt][0] = Bs[n * STR + ks * 8 + tig];
                b[nt][1] = Bs[n * STR + ks * 8 + tig + 4];
            }
#pragma unroll
            for (int mt = 0; mt < 4; mt++)
#pragma unroll
                for (int nt = 0; nt < NT; nt++)
                    asm volatile(
                        "mma.sync.aligned.m16n8k8.row.col.f32.tf32.tf32.f32 "
                        "{%0,%1,%2,%3}, {%4,%5,%6,%7}, {%8,%9}, {%0,%1,%2,%3};"
                        : "+f"(c[mt][nt][0]), "+f"(c[mt][nt][1]),
                          "+f"(c[mt][nt][2]), "+f"(c[mt][nt][3])
                        : "r"(a[mt][0]), "r"(a[mt][1]), "r"(a[mt][2]), "r"(a[mt][3]),
                          "r"(b[nt][0]), "r"(b[nt][1]));
        }
        __syncthreads();
    }

#pragma unroll
    for (int mt = 0; mt < 4; mt++)
#pragma unroll
        for (int nt = 0; nt < NT; nt++) {
            int col = wn + nt * 8 + tig * 2;
            int r0  = brow + wm + mt * 16 + gid;
            int r1  = r0 + 8;
            if (r0 < M) {
                *(float2*)(C + (size_t)r0 * Nd + col) = make_float2(c[mt][nt][0], c[mt][nt][1]);
                *(uint32_t*)(Cb + (size_t)r0 * Nd + col) = pack_bf16x2(c[mt][nt][0], c[mt][nt][1]);
            }
            if (r1 < M) {
                *(float2*)(C + (size_t)r1 * Nd + col) = make_float2(c[mt][nt][2], c[mt][nt][3]);
                *(uint32_t*)(Cb + (size_t)r1 * Nd + col) = pack_bf16x2(c[mt][nt][2], c[mt][nt][3]);
            }
        }
}

// ---------------- threefry2x32 key (0,42) ----------------
__device__ __forceinline__ void threefry_0_42(unsigned c0, unsigned c1,
                                              unsigned& o0, unsigned& o1) {
    const unsigned ks0 = 0u, ks1 = 42u, ks2 = 0u ^ 42u ^ 0x1BD11BDAu;
    unsigned x0 = c0 + ks0, x1 = c1 + ks1;
#define TF_RND(r) { x0 += x1; x1 = __funnelshift_l(x1, x1, (r)); x1 ^= x0; }
    TF_RND(13) TF_RND(15) TF_RND(26) TF_RND(6)
    x0 += ks1; x1 += ks2 + 1u;
    TF_RND(17) TF_RND(29) TF_RND(16) TF_RND(24)
    x0 += ks2; x1 += ks0 + 2u;
    TF_RND(13) TF_RND(15) TF_RND(26) TF_RND(6)
    x0 += ks0; x1 += ks1 + 3u;
    TF_RND(17) TF_RND(29) TF_RND(16) TF_RND(24)
    x0 += ks1; x1 += ks2 + 4u;
    TF_RND(13) TF_RND(15) TF_RND(26) TF_RND(6)
    x0 += ks2; x1 += ks0 + 5u;
#undef TF_RND
    o0 = x0; o1 = x1;
}
__device__ __forceinline__ float tf_uniform(unsigned i) {
    unsigned r0, r1;
    threefry_0_42(0u, i, r0, r1);
    unsigned bits = r0 ^ r1;
    return __uint_as_float((bits >> 9) | 0x3f800000u) - 1.0f;
}

// ---------------- layer1 pull-agg: agg1 = dropout(relu(Â h1 + b1)) ---------
__global__ void __launch_bounds__(256) k_agg1(const float* __restrict__ b1) {
    int g    = threadIdx.x >> 5;
    int lane = threadIdx.x & 31;
    int node = blockIdx.x * 8 + g;
    if (node >= N_NODES) return;

    float dn = g_dinv[node];
    float s = dn * dn;
    const float4* hf = (const float4*)(g_h1 + (size_t)node * F_H);
    float4 a0 = hf[lane * 2], a1 = hf[lane * 2 + 1];
    float acc[8] = {a0.x * s, a0.y * s, a0.z * s, a0.w * s,
                    a1.x * s, a1.y * s, a1.z * s, a1.w * s};

    int e0 = g_rowstart[node], e1 = g_rowstart[node + 1];
    int j = e0;
    for (; j + 2 <= e1; j += 2) {
        int s0 = g_csrc[j], s1 = g_csrc[j + 1];
        float n0 = dn * g_dinv[s0], n1 = dn * g_dinv[s1];
        uint4 r0 = ((const uint4*)(g_h1b + (size_t)s0 * F_H))[lane];
        uint4 r1 = ((const uint4*)(g_h1b + (size_t)s1 * F_H))[lane];
        acc[0] = fmaf(n0, bf_lo(r0.x), acc[0]); acc[1] = fmaf(n0, bf_hi(r0.x), acc[1]);
        acc[2] = fmaf(n0, bf_lo(r0.y), acc[2]); acc[3] = fmaf(n0, bf_hi(r0.y), acc[3]);
        acc[4] = fmaf(n0, bf_lo(r0.z), acc[4]); acc[5] = fmaf(n0, bf_hi(r0.z), acc[5]);
        acc[6] = fmaf(n0, bf_lo(r0.w), acc[6]); acc[7] = fmaf(n0, bf_hi(r0.w), acc[7]);
        acc[0] = fmaf(n1, bf_lo(r1.x), acc[0]); acc[1] = fmaf(n1, bf_hi(r1.x), acc[1]);
        acc[2] = fmaf(n1, bf_lo(r1.y), acc[2]); acc[3] = fmaf(n1, bf_hi(r1.y), acc[3]);
        acc[4] = fmaf(n1, bf_lo(r1.z), acc[4]); acc[5] = fmaf(n1, bf_hi(r1.z), acc[5]);
        acc[6] = fmaf(n1, bf_lo(r1.w), acc[6]); acc[7] = fmaf(n1, bf_hi(r1.w), acc[7]);
    }
    if (j < e1) {
        int s0 = g_csrc[j];
        float n0 = dn * g_dinv[s0];
        uint4 r0 = ((const uint4*)(g_h1b + (size_t)s0 * F_H))[lane];
        acc[0] = fmaf(n0, bf_lo(r0.x), acc[0]); acc[1] = fmaf(n0, bf_hi(r0.x), acc[1]);
        acc[2] = fmaf(n0, bf_lo(r0.y), acc[2]); acc[3] = fmaf(n0, bf_hi(r0.y), acc[3]);
        acc[4] = fmaf(n0, bf_lo(r0.z), acc[4]); acc[5] = fmaf(n0, bf_hi(r0.z), acc[5]);
        acc[6] = fmaf(n0, bf_lo(r0.w), acc[6]); acc[7] = fmaf(n0, bf_hi(r0.w), acc[7]);
    }
    const float4 bb0 = ((const float4*)b1)[lane * 2];
    const float4 bb1 = ((const float4*)b1)[lane * 2 + 1];
    float bias[8] = {bb0.x, bb0.y, bb0.z, bb0.w, bb1.x, bb1.y, bb1.z, bb1.w};
    unsigned i0 = (unsigned)node * F_H + lane * 8;
    float outv[8];
#pragma unroll
    for (int q = 0; q < 8; q++) {
        float v = fmaxf(acc[q] + bias[q], 0.0f);
        outv[q] = (tf_uniform(i0 + q) < 0.8f) ? v * 1.25f : 0.0f;
    }
    float4* dst = (float4*)(g_agg1 + (size_t)node * F_H);
    dst[lane * 2]     = make_float4(outv[0], outv[1], outv[2], outv[3]);
    dst[lane * 2 + 1] = make_float4(outv[4], outv[5], outv[6], outv[7]);
}

// ---------------- layer2 pull-agg + bias + softmax -> d_out ----------------
__global__ void __launch_bounds__(256) k_agg2(const float* __restrict__ b2,
                                              float* __restrict__ out) {
    int g    = threadIdx.x >> 5;
    int lane = threadIdx.x & 31;
    int node = blockIdx.x * 8 + g;
    if (node >= N_NODES) return;

    float dn = g_dinv[node];
    float4 acc = ((const float4*)(g_h2 + (size_t)node * F_OUT))[lane];
    float s = dn * dn;
    acc.x *= s; acc.y *= s; acc.z *= s; acc.w *= s;

    int e0 = g_rowstart[node], e1 = g_rowstart[node + 1];
    int j = e0;
    for (; j + 2 <= e1; j += 2) {
        int s0 = g_csrc[j], s1 = g_csrc[j + 1];
        float n0 = dn * g_dinv[s0], n1 = dn * g_dinv[s1];
        uint2 r0 = ((const uint2*)(g_h2b + (size_t)s0 * F_OUT))[lane];
        uint2 r1 = ((const uint2*)(g_h2b + (size_t)s1 * F_OUT))[lane];
        acc.x = fmaf(n0, bf_lo(r0.x), acc.x); acc.y = fmaf(n0, bf_hi(r0.x), acc.y);
        acc.z = fmaf(n0, bf_lo(r0.y), acc.z); acc.w = fmaf(n0, bf_hi(r0.y), acc.w);
        acc.x = fmaf(n1, bf_lo(r1.x), acc.x); acc.y = fmaf(n1, bf_hi(r1.x), acc.y);
        acc.z = fmaf(n1, bf_lo(r1.y), acc.z); acc.w = fmaf(n1, bf_hi(r1.y), acc.w);
    }
    if (j < e1) {
        int s0 = g_csrc[j];
        float n0 = dn * g_dinv[s0];
        uint2 r0 = ((const uint2*)(g_h2b + (size_t)s0 * F_OUT))[lane];
        acc.x = fmaf(n0, bf_lo(r0.x), acc.x); acc.y = fmaf(n0, bf_hi(r0.x), acc.y);
        acc.z = fmaf(n0, bf_lo(r0.y), acc.z); acc.w = fmaf(n0, bf_hi(r0.y), acc.w);
    }
    float4 bb = ((const float4*)b2)[lane];
    acc.x += bb.x; acc.y += bb.y; acc.z += bb.z; acc.w += bb.w;

    float m = fmaxf(fmaxf(acc.x, acc.y), fmaxf(acc.z, acc.w));
#pragma unroll
    for (int off = 16; off > 0; off >>= 1)
        m = fmaxf(m, __shfl_xor_sync(0xffffffffu, m, off));
    acc.x = expf(acc.x - m); acc.y = expf(acc.y - m);
    acc.z = expf(acc.z - m); acc.w = expf(acc.w - m);
    float sum = acc.x + acc.y + acc.z + acc.w;
#pragma unroll
    for (int off = 16; off > 0; off >>= 1)
        sum += __shfl_xor_sync(0xffffffffu, sum, off);
    float inv = 1.0f / sum;
    acc.x *= inv; acc.y *= inv; acc.z *= inv; acc.w *= inv;
    ((float4*)(out + (size_t)node * F_OUT))[lane] = acc;
}

// ---------------- launcher (fork-join: CSR build overlaps GEMM1) ----------
extern "C" void kernel_launch(void* const* d_in, const int* in_sizes, int n_in,
                              void* d_out, int out_size) {
    const float* x  = (const float*)d_in[0];
    const void*  ei = d_in[1];
    const float* W1 = (const float*)d_in[2];
    const float* b1 = (const float*)d_in[3];
    const float* W2 = (const float*)d_in[4];
    const float* b2 = (const float*)d_in[5];
    float* out = (float*)d_out;

    float* h1;   cudaGetSymbolAddress((void**)&h1,   g_h1);
    float* agg1; cudaGetSymbolAddress((void**)&agg1, g_agg1);
    float* h2;   cudaGetSymbolAddress((void**)&h2,   g_h2);
    uint16_t* h1b; cudaGetSymbolAddress((void**)&h1b, g_h1b);
    uint16_t* h2b; cudaGetSymbolAddress((void**)&h2b, g_h2b);
    uint32_t* w1t; cudaGetSymbolAddress((void**)&w1t, g_w1t);
    uint32_t* w2t; cudaGetSymbolAddress((void**)&w2t, g_w2t);

    constexpr int STRB = 36 * 4;
    constexpr int SMEM1 = 3 * 128 * STRB + 3 * F_H  * STRB;  // 165888
    constexpr int SMEM2 = 3 * 128 * STRB + 3 * F_OUT * STRB; // 110592
    cudaFuncSetAttribute(k_gemm_mma<F_IN, F_H>,
                         cudaFuncAttributeMaxDynamicSharedMemorySize, SMEM1);
    cudaFuncSetAttribute(k_gemm_mma<F_H, F_OUT>,
                         cudaFuncAttributeMaxDynamicSharedMemorySize, SMEM2);

    const int MTILES = (N_NODES + 127) / 128;  // 391

    // one-time resource init (streams/events; identical launched work per call)
    static cudaStream_t s_side = []() {
        cudaStream_t s; cudaStreamCreateWithFlags(&s, cudaStreamNonBlocking); return s;
    }();
    static cudaEvent_t ev_fork = []() {
        cudaEvent_t e; cudaEventCreateWithFlags(&e, cudaEventDisableTiming); return e;
    }();
    static cudaEvent_t ev_join = []() {
        cudaEvent_t e; cudaEventCreateWithFlags(&e, cudaEventDisableTiming); return e;
    }();

    // ---- fork: side stream builds CSR while main stream runs wprep+GEMM1 ----
    cudaEventRecord(ev_fork, 0);
    cudaStreamWaitEvent(s_side, ev_fork, 0);

    // side chain (CSR build)
    k_detect<<<1, 1024, 0, s_side>>>((const int*)ei);
    k_zero<<<(N_NODES + 255) / 256, 256, 0, s_side>>>();
    k_degree<<<(E_EDGES + 255) / 256, 256, 0, s_side>>>(ei);
    k_scan1<<<SCAN_NB, SCAN_B, 0, s_side>>>();
    k_scan2<<<1, 64, 0, s_side>>>();
    k_scan3<<<(N_NODES + 255) / 256, 256, 0, s_side>>>();
    k_fill<<<(E_EDGES + 255) / 256, 256, 0, s_side>>>(ei);
    cudaEventRecord(ev_join, s_side);

    // main chain (weights + GEMM1)
    k_wprep<F_IN, F_H ><<<(F_IN * F_H  + 255) / 256, 256>>>(W1, w1t);
    k_wprep<F_H,  F_OUT><<<(F_H * F_OUT + 255) / 256, 256>>>(W2, w2t);
    k_gemm_mma<F_IN, F_H><<<MTILES, 512, SMEM1>>>(x, w1t, h1, h1b, N_NODES);

    // ---- join: agg1 needs GEMM1 (main) + CSR/dinv (side) ----
    cudaStreamWaitEvent(0, ev_join, 0);
    k_agg1<<<(N_NODES + 7) / 8, 256>>>(b1);
    k_gemm_mma<F_H, F_OUT><<<MTILES, 512, SMEM2>>>(agg1, w2t, h2, h2b, N_NODES);
    k_agg2<<<(N_NODES + 7) / 8, 256>>>(b2, out);
}